// round 1
// baseline (speedup 1.0000x reference)
#include <cuda_runtime.h>
#include <math.h>

// Problem constants
#define CB 2
#define CT 16
#define CD 64
#define CH 48
#define CW 48
#define CE 4
#define CF 128
#define CBT (CB*CT)         // 32
#define CHW (CH*CW)         // 2304
#define NPIX (CBT*CHW)      // 73728
#define C2D (2*CD)          // 128

// ---------------------------------------------------------------------------
// Scratch (static device memory; no allocation at runtime)
// ---------------------------------------------------------------------------
__device__ float  g_xn[(size_t)CBT*C2D*CHW];        // conv input (bt,c,h,w)
__device__ float  g_xs_re[(size_t)CBT*CD*CHW];      // post-conv residual (bt,d,h,w)
__device__ float  g_xs_im[(size_t)CBT*CD*CHW];
__device__ float2 g_xeig[(size_t)NPIX*CD];          // (pix,d) complex; reused as delta
__device__ float2 g_xc[(size_t)NPIX*CD];            // decoded + LN'd (pix,d)
__device__ float2 g_act[(size_t)NPIX*CE*CF];        // MLP hidden (pix, e*F+f)
__device__ float  g_gates[(size_t)NPIX*CE];
__device__ float2 g_xmean[CB*CT*CD];
__device__ float  g_gatec[CB*CT*CD];
__device__ float2 g_srcc[CB*CT*CD];
__device__ float2 g_decc[CB*CT*CD];
__device__ float2 g_opfc[CB*CT*CD];

__device__ __forceinline__ float2 cmul(float2 a, float2 b) {
    return make_float2(a.x*b.x - a.y*b.y, a.x*b.y + a.y*b.x);
}
__device__ __forceinline__ float geluf(float x) {
    float x3 = x*x*x;
    return 0.5f*x*(1.0f + tanhf(0.7978845608028654f*(x + 0.044715f*x3)));
}

// ---------------------------------------------------------------------------
// K1: spatial LayerNorm over 128 channels ([re;im]) + metric -> g_xn
// one thread per pixel; lanes along w => coalesced per-channel loads
// ---------------------------------------------------------------------------
__global__ void k_ln_spatial(const float* __restrict__ xre, const float* __restrict__ xim,
                             const float* __restrict__ w, const float* __restrict__ b,
                             const float* __restrict__ metric)
{
    int pix = blockIdx.x*blockDim.x + threadIdx.x;
    if (pix >= NPIX) return;
    int bt = pix / CHW, hw = pix % CHW;
    size_t base = (size_t)bt*CD*CHW + hw;
    float s = 0.f, ss = 0.f;
    #pragma unroll 4
    for (int c = 0; c < C2D; c++) {
        float v = (c < CD) ? xre[base + (size_t)c*CHW] : xim[base + (size_t)(c-CD)*CHW];
        s += v; ss += v*v;
    }
    float mean = s * (1.f/128.f);
    float var  = ss * (1.f/128.f) - mean*mean;
    float inv  = rsqrtf(var + 1e-5f);
    float met  = metric[hw];
    size_t obase = (size_t)bt*C2D*CHW + hw;
    #pragma unroll 4
    for (int c = 0; c < C2D; c++) {
        float v = (c < CD) ? xre[base + (size_t)c*CHW] : xim[base + (size_t)(c-CD)*CHW];
        g_xn[obase + (size_t)c*CHW] = ((v - mean)*inv*w[c] + b[c]) * met;
    }
}

// ---------------------------------------------------------------------------
// K2: 3x3 conv 128->128 SAME + bias + complex residual -> g_xs_re/g_xs_im
// grid (tile 0..8, ocgroup 0..3, bt 0..31); 256 threads
// each thread: 2x2 pixels x 8 output channels
// ---------------------------------------------------------------------------
__global__ void k_conv(const float* __restrict__ cw, const float* __restrict__ cb,
                       const float* __restrict__ xre, const float* __restrict__ xim)
{
    __shared__ float s_in[8][18][18];
    __shared__ float s_w[32][8][9];
    int tile = blockIdx.x, ocg = blockIdx.y, bt = blockIdx.z;
    int ty0 = (tile/3)*16, tx0 = (tile%3)*16;
    int tid = threadIdx.x;
    int qid = tid & 63, osub = tid >> 6;     // 64 quads, 4 oc-subgroups
    int qy = qid >> 3, qx = qid & 7;

    float acc[8][4];
    #pragma unroll
    for (int o = 0; o < 8; o++) { acc[o][0]=0.f; acc[o][1]=0.f; acc[o][2]=0.f; acc[o][3]=0.f; }

    for (int cc = 0; cc < 16; cc++) {        // 16 chunks of 8 input channels
        for (int i = tid; i < 8*18*18; i += 256) {
            int ic = i/324, rem = i%324, r = rem/18, c = rem%18;
            int gy = ty0 + r - 1, gx = tx0 + c - 1;
            float v = 0.f;
            if (gy >= 0 && gy < CH && gx >= 0 && gx < CW)
                v = g_xn[((size_t)(bt*C2D + cc*8 + ic)*CH + gy)*CW + gx];
            s_in[ic][r][c] = v;
        }
        for (int i = tid; i < 32*8*9; i += 256) {
            int oc = i/72, rem = i%72, ic = rem/9, k = rem%9;
            s_w[oc][ic][k] = cw[((size_t)(ocg*32 + oc)*C2D + cc*8 + ic)*9 + k];
        }
        __syncthreads();
        #pragma unroll
        for (int ic = 0; ic < 8; ic++) {
            float iv[4][4];
            #pragma unroll
            for (int r = 0; r < 4; r++)
                #pragma unroll
                for (int c = 0; c < 4; c++)
                    iv[r][c] = s_in[ic][qy*2 + r][qx*2 + c];
            #pragma unroll
            for (int o = 0; o < 8; o++) {
                #pragma unroll
                for (int ky = 0; ky < 3; ky++)
                    #pragma unroll
                    for (int kx = 0; kx < 3; kx++) {
                        float wv = s_w[osub*8 + o][ic][ky*3 + kx];
                        acc[o][0] = fmaf(wv, iv[ky  ][kx  ], acc[o][0]);
                        acc[o][1] = fmaf(wv, iv[ky  ][kx+1], acc[o][1]);
                        acc[o][2] = fmaf(wv, iv[ky+1][kx  ], acc[o][2]);
                        acc[o][3] = fmaf(wv, iv[ky+1][kx+1], acc[o][3]);
                    }
            }
        }
        __syncthreads();
    }
    #pragma unroll
    for (int o = 0; o < 8; o++) {
        int ocG = ocg*32 + osub*8 + o;
        float bias = cb[ocG];
        #pragma unroll
        for (int q = 0; q < 4; q++) {
            int py = ty0 + qy*2 + (q >> 1);
            int px = tx0 + qx*2 + (q & 1);
            float val = acc[o][q] + bias;
            if (ocG < CD) {
                size_t idx = ((size_t)(bt*CD + ocG)*CH + py)*CW + px;
                g_xs_re[idx] = xre[idx] + val;
            } else {
                size_t idx = ((size_t)(bt*CD + ocG - CD)*CH + py)*CW + px;
                g_xs_im[idx] = xim[idx] + val;
            }
        }
    }
}

// ---------------------------------------------------------------------------
// Generic complex GEMM: C[m,n] = sum_k A[m,k]*B[k,n] (complex), BM=BN=64, BK=16
// ALAY: 0 = row-major float2 A (ld = lda); 1 = planar (g_xs_re/g_xs_im geometry)
// EPI : 0 = none; 1 = gelu(re/im) * gates[m*4 + z]
// grid.z indexes weight slice (B += z*zBoff, C += z*zCoff)
// ---------------------------------------------------------------------------
template<int ALAY, int EPI>
__global__ void k_cgemm(const float2* __restrict__ A2,
                        const float* __restrict__ Apre, const float* __restrict__ Apim,
                        const float* __restrict__ Bre, const float* __restrict__ Bim,
                        float2* __restrict__ C,
                        const float* __restrict__ gates,
                        int K, int lda, int ldb, int ldc, int zBoff, int zCoff)
{
    __shared__ float2 As[16][66];
    __shared__ float2 Bs[16][66];
    const int bm = blockIdx.y * 64;
    const int bn = blockIdx.x * 64;
    const int z  = blockIdx.z;
    Bre += (size_t)z * zBoff; Bim += (size_t)z * zBoff;
    C   += (size_t)z * zCoff;

    int tid = threadIdx.x;
    int ty = tid >> 4, tx = tid & 15;
    float2 acc[4][4];
    #pragma unroll
    for (int i = 0; i < 4; i++)
        #pragma unroll
        for (int j = 0; j < 4; j++) acc[i][j] = make_float2(0.f, 0.f);

    int bt = 0, hwb = 0;
    if (ALAY == 1) { bt = bm / CHW; hwb = bm % CHW; }

    for (int k0 = 0; k0 < K; k0 += 16) {
        if (ALAY == 0) {
            #pragma unroll
            for (int i = 0; i < 4; i++) {
                int lin = tid + i*256;
                int m = lin >> 4, k = lin & 15;      // k-fast: coalesced
                As[k][m] = A2[(size_t)(bm + m)*lda + (k0 + k)];
            }
        } else {
            #pragma unroll
            for (int i = 0; i < 4; i++) {
                int lin = tid + i*256;
                int m = lin & 63, k = lin >> 6;      // m-fast: coalesced in planar layout
                size_t gi = (size_t)(bt*CD + k0 + k)*CHW + hwb + m;
                As[k][m] = make_float2(Apre[gi], Apim[gi]);
            }
        }
        #pragma unroll
        for (int i = 0; i < 4; i++) {
            int lin = tid + i*256;
            int n = lin & 63, k = lin >> 6;          // n-fast: coalesced
            size_t gi = (size_t)(k0 + k)*ldb + bn + n;
            Bs[k][n] = make_float2(Bre[gi], Bim[gi]);
        }
        __syncthreads();
        #pragma unroll
        for (int kk = 0; kk < 16; kk++) {
            float2 af[4], bf[4];
            #pragma unroll
            for (int i = 0; i < 4; i++) af[i] = As[kk][ty*4 + i];
            #pragma unroll
            for (int j = 0; j < 4; j++) bf[j] = Bs[kk][tx*4 + j];
            #pragma unroll
            for (int i = 0; i < 4; i++)
                #pragma unroll
                for (int j = 0; j < 4; j++) {
                    acc[i][j].x = fmaf(af[i].x, bf[j].x, acc[i][j].x);
                    acc[i][j].x = fmaf(-af[i].y, bf[j].y, acc[i][j].x);
                    acc[i][j].y = fmaf(af[i].x, bf[j].y, acc[i][j].y);
                    acc[i][j].y = fmaf(af[i].y, bf[j].x, acc[i][j].y);
                }
        }
        __syncthreads();
    }
    #pragma unroll
    for (int i = 0; i < 4; i++) {
        int m = bm + ty*4 + i;
        #pragma unroll
        for (int j = 0; j < 4; j++) {
            int n = bn + tx*4 + j;
            float2 v = acc[i][j];
            if (EPI == 1) {
                float g = gates[(size_t)m*CE + z];
                v.x = geluf(v.x) * g;
                v.y = geluf(v.y) * g;
            }
            C[(size_t)m*ldc + n] = v;
        }
    }
}

// ---------------------------------------------------------------------------
// K4: mean over H*W  (x_eig -> x_mean)
// ---------------------------------------------------------------------------
__global__ void k_mean()
{
    int bt = blockIdx.x, tid = threadIdx.x;
    int d = tid & 63, grp = tid >> 6;
    float2 acc = make_float2(0.f, 0.f);
    for (int hw = grp; hw < CHW; hw += 4) {
        float2 v = g_xeig[(size_t)(bt*CHW + hw)*CD + d];
        acc.x += v.x; acc.y += v.y;
    }
    __shared__ float2 red[256];
    red[tid] = acc;
    __syncthreads();
    if (tid < 64) {
        float2 t = red[tid];
        t.x += red[tid+64].x + red[tid+128].x + red[tid+192].x;
        t.y += red[tid+64].y + red[tid+128].y + red[tid+192].y;
        g_xmean[bt*CD + tid] = make_float2(t.x * (1.f/CHW), t.y * (1.f/CHW));
    }
}

// ---------------------------------------------------------------------------
// K5: flux scan + lambda / decay / forcing coefficients (tiny)
// ---------------------------------------------------------------------------
__global__ void k_scan(const float* __restrict__ dt,
                       const float* __restrict__ fpre, const float* __restrict__ fpim,
                       const float* __restrict__ Wg, const float* __restrict__ bg,
                       const float* __restrict__ are, const float* __restrict__ aim,
                       const float* __restrict__ lnu, const float* __restrict__ limv)
{
    int tid = threadIdx.x;
    if (tid >= CB*CD) return;
    int b = tid >> 6, d = tid & 63;
    float x = lnu[d];
    float sp = (x > 20.f) ? x : log1pf(expf(x));
    float lre = -sp - 1e-4f;
    float lim = limv[d];
    float den = lre*lre + lim*lim;
    float2 alpha = make_float2(are[d], aim[d]);
    float2 flux  = make_float2(fpre[b*CD + d], fpim[b*CD + d]);
    for (int t = 0; t < CT; t++) {
        int base = (b*CT + t)*CD;
        float s = bg[d];
        for (int k = 0; k < CD; k++)
            s = fmaf(g_xmean[base + k].x, Wg[k*CD + d], s);
        float g = 1.f / (1.f + expf(-s));
        float2 xm = g_xmean[base + d];
        float2 nf = make_float2(flux.x*g + xm.x*(1.f - g), flux.y*g + xm.y*(1.f - g));
        flux = nf;
        float2 src = cmul(nf, alpha);
        float dtv = dt[t];
        float er = expf(lre*dtv), ph = lim*dtv;
        float2 dec = make_float2(er*cosf(ph), er*sinf(ph));
        float nr = dec.x - 1.f, ni = dec.y;
        float2 opf = make_float2((nr*lre + ni*lim)/den, (ni*lre - nr*lim)/den);
        int idx = base + d;
        g_gatec[idx] = g; g_srcc[idx] = src; g_decc[idx] = dec; g_opfc[idx] = opf;
    }
}

// ---------------------------------------------------------------------------
// K6: forcing + temporal associative scan + h_prev term (in-place on g_xeig)
// ---------------------------------------------------------------------------
__global__ void k_temporal(const float* __restrict__ hre, const float* __restrict__ him)
{
    int idx = blockIdx.x*blockDim.x + threadIdx.x;     // (b,hw,d)
    if (idx >= CB*CHW*CD) return;
    int d = idx & 63;
    int hw = (idx >> 6) % CHW;
    int b = idx / (CHW*CD);
    float2 hp = make_float2(hre[idx], him[idx]);       // layout matches (b,h,w,d)
    float2 y = make_float2(0.f, 0.f);
    for (int t = 0; t < CT; t++) {
        int ci = (b*CT + t)*CD + d;
        float g = g_gatec[ci];
        float2 src = g_srcc[ci], dec = g_decc[ci], opf = g_opfc[ci];
        size_t ei = (size_t)((b*CT + t)*CHW + hw)*CD + d;
        float2 xe = g_xeig[ei];
        float2 f = make_float2(xe.x*g + src.x*(1.f - g), xe.y*g + src.y*(1.f - g));
        float2 ut = cmul(f, opf);
        float2 yn = cmul(dec, y);
        y = make_float2(yn.x + ut.x, yn.y + ut.y);
        float2 hd = cmul(hp, dec);
        g_xeig[ei] = make_float2(y.x + hd.x, y.y + hd.y);
    }
}

// ---------------------------------------------------------------------------
// K8: temporal LayerNorm (in-place on g_xc) + softmax gates  — warp per pixel
// ---------------------------------------------------------------------------
__global__ void k_ln2gate(const float* __restrict__ w, const float* __restrict__ b,
                          const float* __restrict__ Wgate)
{
    int gwarp = (blockIdx.x*blockDim.x + threadIdx.x) >> 5;
    int lane = threadIdx.x & 31;
    if (gwarp >= NPIX) return;
    size_t base = (size_t)gwarp * CD;
    float2 v0 = g_xc[base + lane];
    float2 v1 = g_xc[base + 32 + lane];
    float s  = v0.x + v0.y + v1.x + v1.y;
    float ss = v0.x*v0.x + v0.y*v0.y + v1.x*v1.x + v1.y*v1.y;
    #pragma unroll
    for (int o = 16; o; o >>= 1) {
        s  += __shfl_xor_sync(0xffffffffu, s, o);
        ss += __shfl_xor_sync(0xffffffffu, ss, o);
    }
    float mean = s * (1.f/128.f);
    float var  = ss * (1.f/128.f) - mean*mean;
    float inv  = rsqrtf(var + 1e-5f);
    int d0 = lane, d1 = lane + 32;
    float xr0 = (v0.x - mean)*inv*w[d0]      + b[d0];
    float xi0 = (v0.y - mean)*inv*w[CD + d0] + b[CD + d0];
    float xr1 = (v1.x - mean)*inv*w[d1]      + b[d1];
    float xi1 = (v1.y - mean)*inv*w[CD + d1] + b[CD + d1];
    g_xc[base + d0] = make_float2(xr0, xi0);
    g_xc[base + d1] = make_float2(xr1, xi1);
    float pe[CE];
    #pragma unroll
    for (int e = 0; e < CE; e++)
        pe[e] = xr0*Wgate[d0*CE + e] + xr1*Wgate[d1*CE + e];
    #pragma unroll
    for (int e = 0; e < CE; e++)
        #pragma unroll
        for (int o = 16; o; o >>= 1)
            pe[e] += __shfl_xor_sync(0xffffffffu, pe[e], o);
    float m = fmaxf(fmaxf(pe[0], pe[1]), fmaxf(pe[2], pe[3]));
    float e0 = expf(pe[0]-m), e1 = expf(pe[1]-m), e2 = expf(pe[2]-m), e3 = expf(pe[3]-m);
    float denom = e0 + e1 + e2 + e3;
    if (lane == 0) {
        float* gp = &g_gates[(size_t)gwarp*CE];
        gp[0] = e0/denom; gp[1] = e1/denom; gp[2] = e2/denom; gp[3] = e3/denom;
    }
}

// ---------------------------------------------------------------------------
// K11: combine (xc + delta) transpose back to (bt,d,h,w) + residual -> out
// ---------------------------------------------------------------------------
__global__ void k_combine(float2* __restrict__ out)
{
    __shared__ float2 sm[32][65];
    int pix0 = blockIdx.x * 32;
    int bt = pix0 / CHW, hw0 = pix0 % CHW;
    int tid = threadIdx.x;
    #pragma unroll
    for (int i = 0; i < 8; i++) {
        int lin = tid + i*256;
        int p = lin >> 6, d = lin & 63;
        size_t gi = (size_t)(pix0 + p)*CD + d;
        float2 v  = g_xc[gi];
        float2 dl = g_xeig[gi];
        sm[p][d] = make_float2(v.x + dl.x, v.y + dl.y);
    }
    __syncthreads();
    #pragma unroll
    for (int i = 0; i < 8; i++) {
        int lin = tid + i*256;
        int p = lin & 31, d = lin >> 5;
        size_t gi = (size_t)(bt*CD + d)*CHW + hw0 + p;
        float2 v = sm[p][d];
        out[gi] = make_float2(g_xs_re[gi] + v.x, g_xs_im[gi] + v.y);
    }
}

// ---------------------------------------------------------------------------
// Host launcher
// ---------------------------------------------------------------------------
extern "C" void kernel_launch(void* const* d_in, const int* in_sizes, int n_in,
                              void* d_out, int out_size)
{
    const float* x_re   = (const float*)d_in[0];
    const float* x_im   = (const float*)d_in[1];
    const float* hp_re  = (const float*)d_in[2];
    const float* hp_im  = (const float*)d_in[3];
    const float* dt     = (const float*)d_in[4];
    const float* fp_re  = (const float*)d_in[5];
    const float* fp_im  = (const float*)d_in[6];
    const float* lnsp_w = (const float*)d_in[7];
    const float* lnsp_b = (const float*)d_in[8];
    const float* conv_w = (const float*)d_in[9];
    const float* conv_b = (const float*)d_in[10];
    const float* metric = (const float*)d_in[11];
    const float* lnt_w  = (const float*)d_in[12];
    const float* lnt_b  = (const float*)d_in[13];
    const float* Eenc_r = (const float*)d_in[14];
    const float* Eenc_i = (const float*)d_in[15];
    const float* Edec_r = (const float*)d_in[16];
    const float* Edec_i = (const float*)d_in[17];
    const float* Wg     = (const float*)d_in[18];
    const float* bg     = (const float*)d_in[19];
    const float* al_re  = (const float*)d_in[20];
    const float* al_im  = (const float*)d_in[21];
    const float* lam_nu = (const float*)d_in[22];
    const float* lam_im = (const float*)d_in[23];
    const float* Wgate  = (const float*)d_in[24];
    const float* W1_re  = (const float*)d_in[25];
    const float* W1_im  = (const float*)d_in[26];
    const float* W2_re  = (const float*)d_in[27];
    const float* W2_im  = (const float*)d_in[28];

    // device-global scratch pointers (capture-safe, deterministic)
    float2 *p_xeig = 0, *p_xc = 0, *p_act = 0;
    float  *p_xsre = 0, *p_xsim = 0, *p_gates = 0;
    cudaGetSymbolAddress((void**)&p_xeig,  g_xeig);
    cudaGetSymbolAddress((void**)&p_xc,    g_xc);
    cudaGetSymbolAddress((void**)&p_act,   g_act);
    cudaGetSymbolAddress((void**)&p_xsre,  g_xs_re);
    cudaGetSymbolAddress((void**)&p_xsim,  g_xs_im);
    cudaGetSymbolAddress((void**)&p_gates, g_gates);

    // 1. spatial LN + metric
    k_ln_spatial<<<(NPIX + 255)/256, 256>>>(x_re, x_im, lnsp_w, lnsp_b, metric);

    // 2. conv 3x3 + bias + residual
    k_conv<<<dim3(9, 4, CBT), 256>>>(conv_w, conv_b, x_re, x_im);

    // 3. x_eig = xs @ E_enc   (planar A)
    k_cgemm<1,0><<<dim3(1, NPIX/64, 1), 256>>>(
        nullptr, p_xsre, p_xsim, Eenc_r, Eenc_i, p_xeig, nullptr,
        CD, 0, CD, CD, 0, 0);

    // 4. mean over H*W
    k_mean<<<CBT, 256>>>();

    // 5. flux scan + coefficients
    k_scan<<<1, 128>>>(dt, fp_re, fp_im, Wg, bg, al_re, al_im, lam_nu, lam_im);

    // 6. forcing + temporal scan + h_prev
    k_temporal<<<(CB*CHW*CD + 255)/256, 256>>>(hp_re, hp_im);

    // 7. xc_raw = u @ E_dec
    k_cgemm<0,0><<<dim3(1, NPIX/64, 1), 256>>>(
        p_xeig, nullptr, nullptr, Edec_r, Edec_i, p_xc, nullptr,
        CD, CD, CD, CD, 0, 0);

    // 8. temporal LN (in-place) + softmax gates
    k_ln2gate<<<NPIX/8, 256>>>(lnt_w, lnt_b, Wgate);

    // 9. h1 per e (gelu * gate epilogue) -> g_act laid out (m, e*F+f)
    k_cgemm<0,1><<<dim3(CF/64, NPIX/64, CE), 256>>>(
        p_xc, nullptr, nullptr, W1_re, W1_im, p_act, p_gates,
        CD, CD, CF, CE*CF, CD*CF, CF);

    // 10. delta = a_scaled @ W2(viewed as (E*F, D))  -> g_xeig (reuse)
    k_cgemm<0,0><<<dim3(1, NPIX/64, 1), 256>>>(
        p_act, nullptr, nullptr, W2_re, W2_im, p_xeig, nullptr,
        CE*CF, CE*CF, CD, CD, 0, 0);

    // 11. combine + transpose + final residual -> out
    k_combine<<<NPIX/32, 256>>>((float2*)d_out);
}

// round 3
// speedup vs baseline: 1.1828x; 1.1828x over previous
#include <cuda_runtime.h>
#include <math.h>
#include <stdint.h>

// Problem constants
#define CB 2
#define CT 16
#define CD 64
#define CH 48
#define CW 48
#define CE 4
#define CF 128
#define CBT (CB*CT)         // 32
#define CHW (CH*CW)         // 2304
#define NPIX (CBT*CHW)      // 73728
#define C2D (2*CD)          // 128

// ---------------------------------------------------------------------------
// Scratch (static device memory; no allocation at runtime)
// ---------------------------------------------------------------------------
__device__ float  g_xn[(size_t)CBT*C2D*CHW];        // conv input (bt,c,h,w)
__device__ float  g_xs_re[(size_t)CBT*CD*CHW];      // post-conv residual (bt,d,h,w)
__device__ float  g_xs_im[(size_t)CBT*CD*CHW];
__device__ float2 g_xeig[(size_t)NPIX*CD];          // (pix,d) complex; reused as delta
__device__ float2 g_xc[(size_t)NPIX*CD];            // decoded + LN'd (pix,d)
__device__ float2 g_act[(size_t)NPIX*CE*CF];        // MLP hidden (pix, e*F+f)
__device__ float  g_gates[(size_t)NPIX*CE];
__device__ float2 g_mpart[(size_t)CBT*12*CD];
__device__ float2 g_xmean[CB*CT*CD];
__device__ float  g_gatec[CB*CT*CD];
__device__ float2 g_srcc[CB*CT*CD];
__device__ float2 g_decc[CB*CT*CD];
__device__ float2 g_opfc[CB*CT*CD];

__device__ __forceinline__ float2 cmul(float2 a, float2 b) {
    return make_float2(a.x*b.x - a.y*b.y, a.x*b.y + a.y*b.x);
}
__device__ __forceinline__ float geluf(float x) {
    float x3 = x*x*x;
    return 0.5f*x*(1.0f + tanhf(0.7978845608028654f*(x + 0.044715f*x3)));
}
__device__ __forceinline__ uint32_t f2tf(float f) {
    uint32_t u; asm("cvt.rna.tf32.f32 %0, %1;" : "=r"(u) : "f"(f)); return u;
}

#define MMA_TF32(d, a, b0, b1) \
  asm volatile("mma.sync.aligned.m16n8k8.row.col.f32.tf32.tf32.f32 " \
    "{%0,%1,%2,%3}, {%4,%5,%6,%7}, {%8,%9}, {%0,%1,%2,%3};" \
    : "+f"((d)[0]),"+f"((d)[1]),"+f"((d)[2]),"+f"((d)[3]) \
    : "r"((a)[0]),"r"((a)[1]),"r"((a)[2]),"r"((a)[3]), "r"(b0),"r"(b1))

// ---------------------------------------------------------------------------
// K1: spatial LayerNorm over 128 channels ([re;im]) + metric -> g_xn
// ---------------------------------------------------------------------------
__global__ void k_ln_spatial(const float* __restrict__ xre, const float* __restrict__ xim,
                             const float* __restrict__ w, const float* __restrict__ b,
                             const float* __restrict__ metric)
{
    int pix = blockIdx.x*blockDim.x + threadIdx.x;
    if (pix >= NPIX) return;
    int bt = pix / CHW, hw = pix % CHW;
    size_t base = (size_t)bt*CD*CHW + hw;
    float s = 0.f, ss = 0.f;
    #pragma unroll 4
    for (int c = 0; c < C2D; c++) {
        float v = (c < CD) ? xre[base + (size_t)c*CHW] : xim[base + (size_t)(c-CD)*CHW];
        s += v; ss += v*v;
    }
    float mean = s * (1.f/128.f);
    float var  = ss * (1.f/128.f) - mean*mean;
    float inv  = rsqrtf(var + 1e-5f);
    float met  = metric[hw];
    size_t obase = (size_t)bt*C2D*CHW + hw;
    #pragma unroll 4
    for (int c = 0; c < C2D; c++) {
        float v = (c < CD) ? xre[base + (size_t)c*CHW] : xim[base + (size_t)(c-CD)*CHW];
        g_xn[obase + (size_t)c*CHW] = ((v - mean)*inv*w[c] + b[c]) * met;
    }
}

// ---------------------------------------------------------------------------
// K2: 3x3 conv 128->128 SAME + bias + complex residual -> g_xs_re/g_xs_im
// ---------------------------------------------------------------------------
__global__ void k_conv(const float* __restrict__ cw, const float* __restrict__ cb,
                       const float* __restrict__ xre, const float* __restrict__ xim)
{
    __shared__ float s_in[8][18][18];
    __shared__ float s_w[32][8][9];
    int tile = blockIdx.x, ocg = blockIdx.y, bt = blockIdx.z;
    int ty0 = (tile/3)*16, tx0 = (tile%3)*16;
    int tid = threadIdx.x;
    int qid = tid & 63, osub = tid >> 6;
    int qy = qid >> 3, qx = qid & 7;

    float acc[8][4];
    #pragma unroll
    for (int o = 0; o < 8; o++) { acc[o][0]=0.f; acc[o][1]=0.f; acc[o][2]=0.f; acc[o][3]=0.f; }

    for (int cc = 0; cc < 16; cc++) {
        for (int i = tid; i < 8*18*18; i += 256) {
            int ic = i/324, rem = i%324, r = rem/18, c = rem%18;
            int gy = ty0 + r - 1, gx = tx0 + c - 1;
            float v = 0.f;
            if (gy >= 0 && gy < CH && gx >= 0 && gx < CW)
                v = g_xn[((size_t)(bt*C2D + cc*8 + ic)*CH + gy)*CW + gx];
            s_in[ic][r][c] = v;
        }
        for (int i = tid; i < 32*8*9; i += 256) {
            int oc = i/72, rem = i%72, ic = rem/9, k = rem%9;
            s_w[oc][ic][k] = cw[((size_t)(ocg*32 + oc)*C2D + cc*8 + ic)*9 + k];
        }
        __syncthreads();
        #pragma unroll
        for (int ic = 0; ic < 8; ic++) {
            float iv[4][4];
            #pragma unroll
            for (int r = 0; r < 4; r++)
                #pragma unroll
                for (int c = 0; c < 4; c++)
                    iv[r][c] = s_in[ic][qy*2 + r][qx*2 + c];
            #pragma unroll
            for (int o = 0; o < 8; o++) {
                #pragma unroll
                for (int ky = 0; ky < 3; ky++)
                    #pragma unroll
                    for (int kx = 0; kx < 3; kx++) {
                        float wv = s_w[osub*8 + o][ic][ky*3 + kx];
                        acc[o][0] = fmaf(wv, iv[ky  ][kx  ], acc[o][0]);
                        acc[o][1] = fmaf(wv, iv[ky  ][kx+1], acc[o][1]);
                        acc[o][2] = fmaf(wv, iv[ky+1][kx  ], acc[o][2]);
                        acc[o][3] = fmaf(wv, iv[ky+1][kx+1], acc[o][3]);
                    }
            }
        }
        __syncthreads();
    }
    #pragma unroll
    for (int o = 0; o < 8; o++) {
        int ocG = ocg*32 + osub*8 + o;
        float bias = cb[ocG];
        #pragma unroll
        for (int q = 0; q < 4; q++) {
            int py = ty0 + qy*2 + (q >> 1);
            int px = tx0 + qx*2 + (q & 1);
            float val = acc[o][q] + bias;
            if (ocG < CD) {
                size_t idx = ((size_t)(bt*CD + ocG)*CH + py)*CW + px;
                g_xs_re[idx] = xre[idx] + val;
            } else {
                size_t idx = ((size_t)(bt*CD + ocG - CD)*CH + py)*CW + px;
                g_xs_im[idx] = xim[idx] + val;
            }
        }
    }
}

// ---------------------------------------------------------------------------
// Complex GEMM on tensor cores (tf32 mma.sync m16n8k8).
// C[m,n] = sum_k A[m,k]*B[k,n] (complex), via doubled-K real GEMMs:
//   C_re = A_rl @ [Br; -Bi],  C_im = A_rl @ [Bi; Br]
// where A_rl[m][2d+p] is exactly the float2-interleaved memory layout of A.
// Block tile: M=128 pixels x N=64 complex. 8 warps, warp tile 32x32.
// ALAY: 0 = interleaved float2 A (as float*, row stride ldaF floats)
//       1 = planar (g_xs_re/g_xs_im geometry, (bt,d,hw))
// EPI : 0 = none; 1 = gelu(re/im) * gates[m*4 + z]
// ---------------------------------------------------------------------------
template<int ALAY, int EPI>
__global__ void k_mma(const float* __restrict__ A,
                      const float* __restrict__ Apre, const float* __restrict__ Apim,
                      const float* __restrict__ Bre, const float* __restrict__ Bim,
                      float2* __restrict__ C,
                      const float* __restrict__ gates,
                      int Kc, int ldaF, int ldb, int ldc, int zBoff, int zCoff)
{
    __shared__ uint32_t As[128][36];       // padded: bank-conflict-free frag reads
    __shared__ uint32_t Bs[2][32][68];     // [reC/imC][k_real][n]
    const int bm = blockIdx.y * 128;
    const int bn = blockIdx.x * 64;
    const int z  = blockIdx.z;
    Bre += (size_t)z * zBoff; Bim += (size_t)z * zBoff;
    C   += (size_t)z * zCoff;

    int tid = threadIdx.x;
    int wid = tid >> 5, lane = tid & 31;
    int wm = wid & 3, wn = wid >> 2;       // 4 m-warps x 2 n-warps

    int bt = 0, hwb = 0;
    if (ALAY == 1) { bt = bm / CHW; hwb = bm % CHW; }

    float acc[2][4][8];                    // [m-sub][n-sub][re0..3, im0..3]
    #pragma unroll
    for (int i = 0; i < 2; i++)
        #pragma unroll
        for (int j = 0; j < 4; j++)
            #pragma unroll
            for (int q = 0; q < 8; q++) acc[i][j][q] = 0.f;

    const int KR = 2*Kc;
    for (int c0 = 0; c0 < KR; c0 += 32) {
        // --- load A tile (128 x 32 reals) ---
        if (ALAY == 0) {
            #pragma unroll
            for (int t = 0; t < 16; t++) {
                int lin = tid + t*256;
                int m = lin >> 5, k = lin & 31;          // k-fast: coalesced
                As[m][k] = f2tf(A[(size_t)(bm + m)*ldaF + c0 + k]);
            }
        } else {
            #pragma unroll
            for (int t = 0; t < 16; t++) {
                int lin = tid + t*256;
                int m = lin & 127, k = lin >> 7;         // m-fast: coalesced planar
                int g = c0 + k, d = g >> 1;
                const float* P = (g & 1) ? Apim : Apre;
                As[m][k] = f2tf(P[(size_t)(bt*CD + d)*CHW + hwb + m]);
            }
        }
        // --- load combined B tiles (2 x 32 x 64) ---
        #pragma unroll
        for (int t = 0; t < 16; t++) {
            int lin = tid + t*256;
            int n = lin & 63, k = (lin >> 6) & 31, s = lin >> 11;
            int g = c0 + k, d = g >> 1, par = g & 1;
            size_t gi = (size_t)d*ldb + bn + n;
            float v;
            if (s == 0) v = par ? -Bim[gi] : Bre[gi];
            else        v = par ?  Bre[gi] : Bim[gi];
            Bs[s][k][n] = f2tf(v);
        }
        __syncthreads();
        // --- mma over 4 k-steps of 8 ---
        #pragma unroll
        for (int ks = 0; ks < 4; ks++) {
            int kc = ks*8 + (lane & 3);
            uint32_t a[2][4];
            #pragma unroll
            for (int i = 0; i < 2; i++) {
                int r = wm*32 + i*16 + (lane >> 2);
                a[i][0] = As[r  ][kc];   a[i][1] = As[r+8][kc];
                a[i][2] = As[r  ][kc+4]; a[i][3] = As[r+8][kc+4];
            }
            #pragma unroll
            for (int j = 0; j < 4; j++) {
                int n0 = wn*32 + j*8 + (lane >> 2);
                int kb = ks*8 + (lane & 3);
                uint32_t br0 = Bs[0][kb][n0], br1 = Bs[0][kb+4][n0];
                uint32_t bi0 = Bs[1][kb][n0], bi1 = Bs[1][kb+4][n0];
                #pragma unroll
                for (int i = 0; i < 2; i++) {
                    MMA_TF32(acc[i][j],     a[i], br0, br1);
                    MMA_TF32(acc[i][j] + 4, a[i], bi0, bi1);
                }
            }
        }
        __syncthreads();
    }
    // --- epilogue ---
    #pragma unroll
    for (int i = 0; i < 2; i++) {
        #pragma unroll
        for (int j = 0; j < 4; j++) {
            int rbase = bm + wm*32 + i*16 + (lane >> 2);
            int cbase = bn + wn*32 + j*8 + 2*(lane & 3);
            #pragma unroll
            for (int h = 0; h < 2; h++) {                // c0/c1 then c2/c3 (+8 rows)
                int m = rbase + h*8;
                float re0 = acc[i][j][h*2+0], re1 = acc[i][j][h*2+1];
                float im0 = acc[i][j][h*2+4], im1 = acc[i][j][h*2+5];
                if (EPI == 1) {
                    float g = gates[(size_t)m*CE + z];
                    re0 = geluf(re0)*g; im0 = geluf(im0)*g;
                    re1 = geluf(re1)*g; im1 = geluf(im1)*g;
                }
                float4 v = make_float4(re0, im0, re1, im1);
                *reinterpret_cast<float4*>(&C[(size_t)m*ldc + cbase]) = v;
            }
        }
    }
}

// ---------------------------------------------------------------------------
// K4: partial mean over H*W  (x_eig -> g_mpart), final reduce in k_scan
// ---------------------------------------------------------------------------
__global__ void k_mean_part()
{
    int bt = blockIdx.x, sl = blockIdx.y;
    int tid = threadIdx.x, d = tid & 63, grp = tid >> 6;
    float2 acc = make_float2(0.f, 0.f);
    #pragma unroll 4
    for (int it = 0; it < 48; it++) {
        int hw = sl*192 + it*4 + grp;
        float2 v = g_xeig[(size_t)(bt*CHW + hw)*CD + d];
        acc.x += v.x; acc.y += v.y;
    }
    __shared__ float2 red[256];
    red[tid] = acc;
    __syncthreads();
    if (tid < 64) {
        float2 t = red[tid];
        t.x += red[tid+64].x + red[tid+128].x + red[tid+192].x;
        t.y += red[tid+64].y + red[tid+128].y + red[tid+192].y;
        g_mpart[(size_t)(bt*12 + sl)*CD + tid] = t;
    }
}

// ---------------------------------------------------------------------------
// K5: mean finalize + flux scan + lambda / decay / forcing coefficients
// ---------------------------------------------------------------------------
__global__ void k_scan(const float* __restrict__ dt,
                       const float* __restrict__ fpre, const float* __restrict__ fpim,
                       const float* __restrict__ Wg, const float* __restrict__ bg,
                       const float* __restrict__ are, const float* __restrict__ aim,
                       const float* __restrict__ lnu, const float* __restrict__ limv)
{
    int tid = threadIdx.x;
    if (tid >= CB*CD) return;
    int b = tid >> 6, d = tid & 63;
    for (int t = 0; t < CT; t++) {
        int bt = b*CT + t;
        float2 s = make_float2(0.f, 0.f);
        #pragma unroll
        for (int sl = 0; sl < 12; sl++) {
            float2 v = g_mpart[(size_t)(bt*12 + sl)*CD + d];
            s.x += v.x; s.y += v.y;
        }
        g_xmean[bt*CD + d] = make_float2(s.x * (1.f/CHW), s.y * (1.f/CHW));
    }
    __syncthreads();
    float x = lnu[d];
    float sp = (x > 20.f) ? x : log1pf(expf(x));
    float lre = -sp - 1e-4f;
    float lim = limv[d];
    float den = lre*lre + lim*lim;
    float2 alpha = make_float2(are[d], aim[d]);
    float2 flux  = make_float2(fpre[b*CD + d], fpim[b*CD + d]);
    for (int t = 0; t < CT; t++) {
        int base = (b*CT + t)*CD;
        float s = bg[d];
        for (int k = 0; k < CD; k++)
            s = fmaf(g_xmean[base + k].x, Wg[k*CD + d], s);
        float g = 1.f / (1.f + expf(-s));
        float2 xm = g_xmean[base + d];
        float2 nf = make_float2(flux.x*g + xm.x*(1.f - g), flux.y*g + xm.y*(1.f - g));
        flux = nf;
        float2 src = cmul(nf, alpha);
        float dtv = dt[t];
        float er = expf(lre*dtv), ph = lim*dtv;
        float2 dec = make_float2(er*cosf(ph), er*sinf(ph));
        float nr = dec.x - 1.f, ni = dec.y;
        float2 opf = make_float2((nr*lre + ni*lim)/den, (ni*lre - nr*lim)/den);
        int idx = base + d;
        g_gatec[idx] = g; g_srcc[idx] = src; g_decc[idx] = dec; g_opfc[idx] = opf;
    }
}

// ---------------------------------------------------------------------------
// K6: forcing + temporal associative scan + h_prev term (in-place on g_xeig)
// ---------------------------------------------------------------------------
__global__ void k_temporal(const float* __restrict__ hre, const float* __restrict__ him)
{
    int idx = blockIdx.x*blockDim.x + threadIdx.x;     // (b,hw,d)
    if (idx >= CB*CHW*CD) return;
    int d = idx & 63;
    int hw = (idx >> 6) % CHW;
    int b = idx / (CHW*CD);
    float2 hp = make_float2(hre[idx], him[idx]);
    float2 y = make_float2(0.f, 0.f);
    for (int t = 0; t < CT; t++) {
        int ci = (b*CT + t)*CD + d;
        float g = g_gatec[ci];
        float2 src = g_srcc[ci], dec = g_decc[ci], opf = g_opfc[ci];
        size_t ei = (size_t)((b*CT + t)*CHW + hw)*CD + d;
        float2 xe = g_xeig[ei];
        float2 f = make_float2(xe.x*g + src.x*(1.f - g), xe.y*g + src.y*(1.f - g));
        float2 ut = cmul(f, opf);
        float2 yn = cmul(dec, y);
        y = make_float2(yn.x + ut.x, yn.y + ut.y);
        float2 hd = cmul(hp, dec);
        g_xeig[ei] = make_float2(y.x + hd.x, y.y + hd.y);
    }
}

// ---------------------------------------------------------------------------
// K8: temporal LayerNorm (in-place on g_xc) + softmax gates — warp per pixel
// ---------------------------------------------------------------------------
__global__ void k_ln2gate(const float* __restrict__ w, const float* __restrict__ b,
                          const float* __restrict__ Wgate)
{
    int gwarp = (blockIdx.x*blockDim.x + threadIdx.x) >> 5;
    int lane = threadIdx.x & 31;
    if (gwarp >= NPIX) return;
    size_t base = (size_t)gwarp * CD;
    float2 v0 = g_xc[base + lane];
    float2 v1 = g_xc[base + 32 + lane];
    float s  = v0.x + v0.y + v1.x + v1.y;
    float ss = v0.x*v0.x + v0.y*v0.y + v1.x*v1.x + v1.y*v1.y;
    #pragma unroll
    for (int o = 16; o; o >>= 1) {
        s  += __shfl_xor_sync(0xffffffffu, s, o);
        ss += __shfl_xor_sync(0xffffffffu, ss, o);
    }
    float mean = s * (1.f/128.f);
    float var  = ss * (1.f/128.f) - mean*mean;
    float inv  = rsqrtf(var + 1e-5f);
    int d0 = lane, d1 = lane + 32;
    float xr0 = (v0.x - mean)*inv*w[d0]      + b[d0];
    float xi0 = (v0.y - mean)*inv*w[CD + d0] + b[CD + d0];
    float xr1 = (v1.x - mean)*inv*w[d1]      + b[d1];
    float xi1 = (v1.y - mean)*inv*w[CD + d1] + b[CD + d1];
    g_xc[base + d0] = make_float2(xr0, xi0);
    g_xc[base + d1] = make_float2(xr1, xi1);
    float pe[CE];
    #pragma unroll
    for (int e = 0; e < CE; e++)
        pe[e] = xr0*Wgate[d0*CE + e] + xr1*Wgate[d1*CE + e];
    #pragma unroll
    for (int e = 0; e < CE; e++)
        #pragma unroll
        for (int o = 16; o; o >>= 1)
            pe[e] += __shfl_xor_sync(0xffffffffu, pe[e], o);
    float m = fmaxf(fmaxf(pe[0], pe[1]), fmaxf(pe[2], pe[3]));
    float e0 = expf(pe[0]-m), e1 = expf(pe[1]-m), e2 = expf(pe[2]-m), e3 = expf(pe[3]-m);
    float denom = e0 + e1 + e2 + e3;
    if (lane == 0) {
        float* gp = &g_gates[(size_t)gwarp*CE];
        gp[0] = e0/denom; gp[1] = e1/denom; gp[2] = e2/denom; gp[3] = e3/denom;
    }
}

// ---------------------------------------------------------------------------
// K11: combine (xc + delta) transpose back to (bt,d,h,w) + residual -> out
// ---------------------------------------------------------------------------
__global__ void k_combine(float2* __restrict__ out)
{
    __shared__ float2 sm[32][65];
    int pix0 = blockIdx.x * 32;
    int bt = pix0 / CHW, hw0 = pix0 % CHW;
    int tid = threadIdx.x;
    #pragma unroll
    for (int i = 0; i < 8; i++) {
        int lin = tid + i*256;
        int p = lin >> 6, d = lin & 63;
        size_t gi = (size_t)(pix0 + p)*CD + d;
        float2 v  = g_xc[gi];
        float2 dl = g_xeig[gi];
        sm[p][d] = make_float2(v.x + dl.x, v.y + dl.y);
    }
    __syncthreads();
    #pragma unroll
    for (int i = 0; i < 8; i++) {
        int lin = tid + i*256;
        int p = lin & 31, d = lin >> 5;
        size_t gi = (size_t)(bt*CD + d)*CHW + hw0 + p;
        float2 v = sm[p][d];
        out[gi] = make_float2(g_xs_re[gi] + v.x, g_xs_im[gi] + v.y);
    }
}

// ---------------------------------------------------------------------------
// Host launcher
// ---------------------------------------------------------------------------
extern "C" void kernel_launch(void* const* d_in, const int* in_sizes, int n_in,
                              void* d_out, int out_size)
{
    const float* x_re   = (const float*)d_in[0];
    const float* x_im   = (const float*)d_in[1];
    const float* hp_re  = (const float*)d_in[2];
    const float* hp_im  = (const float*)d_in[3];
    const float* dt     = (const float*)d_in[4];
    const float* fp_re  = (const float*)d_in[5];
    const float* fp_im  = (const float*)d_in[6];
    const float* lnsp_w = (const float*)d_in[7];
    const float* lnsp_b = (const float*)d_in[8];
    const float* conv_w = (const float*)d_in[9];
    const float* conv_b = (const float*)d_in[10];
    const float* metric = (const float*)d_in[11];
    const float* lnt_w  = (const float*)d_in[12];
    const float* lnt_b  = (const float*)d_in[13];
    const float* Eenc_r = (const float*)d_in[14];
    const float* Eenc_i = (const float*)d_in[15];
    const float* Edec_r = (const float*)d_in[16];
    const float* Edec_i = (const float*)d_in[17];
    const float* Wg     = (const float*)d_in[18];
    const float* bg     = (const float*)d_in[19];
    const float* al_re  = (const float*)d_in[20];
    const float* al_im  = (const float*)d_in[21];
    const float* lam_nu = (const float*)d_in[22];
    const float* lam_im = (const float*)d_in[23];
    const float* Wgate  = (const float*)d_in[24];
    const float* W1_re  = (const float*)d_in[25];
    const float* W1_im  = (const float*)d_in[26];
    const float* W2_re  = (const float*)d_in[27];
    const float* W2_im  = (const float*)d_in[28];

    float2 *p_xeig = 0, *p_xc = 0, *p_act = 0;
    float  *p_xsre = 0, *p_xsim = 0, *p_gates = 0;
    cudaGetSymbolAddress((void**)&p_xeig,  g_xeig);
    cudaGetSymbolAddress((void**)&p_xc,    g_xc);
    cudaGetSymbolAddress((void**)&p_act,   g_act);
    cudaGetSymbolAddress((void**)&p_xsre,  g_xs_re);
    cudaGetSymbolAddress((void**)&p_xsim,  g_xs_im);
    cudaGetSymbolAddress((void**)&p_gates, g_gates);

    // 1. spatial LN + metric
    k_ln_spatial<<<(NPIX + 255)/256, 256>>>(x_re, x_im, lnsp_w, lnsp_b, metric);

    // 2. conv 3x3 + bias + residual
    k_conv<<<dim3(9, 4, CBT), 256>>>(conv_w, conv_b, x_re, x_im);

    // 3. x_eig = xs @ E_enc   (planar A, tensor cores)
    k_mma<1,0><<<dim3(1, NPIX/128, 1), 256>>>(
        nullptr, p_xsre, p_xsim, Eenc_r, Eenc_i, p_xeig, nullptr,
        CD, 0, CD, CD, 0, 0);

    // 4. partial mean over H*W
    k_mean_part<<<dim3(CBT, 12), 256>>>();

    // 5. mean finalize + flux scan + coefficients
    k_scan<<<1, 128>>>(dt, fp_re, fp_im, Wg, bg, al_re, al_im, lam_nu, lam_im);

    // 6. forcing + temporal scan + h_prev
    k_temporal<<<(CB*CHW*CD + 255)/256, 256>>>(hp_re, hp_im);

    // 7. xc_raw = u @ E_dec
    k_mma<0,0><<<dim3(1, NPIX/128, 1), 256>>>(
        (const float*)p_xeig, nullptr, nullptr, Edec_r, Edec_i, p_xc, nullptr,
        CD, 2*CD, CD, CD, 0, 0);

    // 8. temporal LN (in-place) + softmax gates
    k_ln2gate<<<NPIX/8, 256>>>(lnt_w, lnt_b, Wgate);

    // 9. h1 per e (gelu * gate epilogue) -> g_act (m, e*F+f)
    k_mma<0,1><<<dim3(CF/64, NPIX/128, CE), 256>>>(
        (const float*)p_xc, nullptr, nullptr, W1_re, W1_im, p_act, p_gates,
        CD, 2*CD, CF, CE*CF, CD*CF, CF);

    // 10. delta = a_scaled @ W2(viewed as (E*F, D)) -> g_xeig (reuse)
    k_mma<0,0><<<dim3(1, NPIX/128, 1), 256>>>(
        (const float*)p_act, nullptr, nullptr, W2_re, W2_im, p_xeig, nullptr,
        CE*CF, 2*CE*CF, CD, CD, 0, 0);

    // 11. combine + transpose + final residual -> out
    k_combine<<<NPIX/32, 256>>>((float2*)d_out);
}

// round 5
// speedup vs baseline: 1.3807x; 1.1673x over previous
#include <cuda_runtime.h>
#include <math.h>
#include <stdint.h>

// Problem constants
#define CB 2
#define CT 16
#define CD 64
#define CH 48
#define CW 48
#define CE 4
#define CF 128
#define CBT (CB*CT)         // 32
#define CHW (CH*CW)         // 2304
#define NPIX (CBT*CHW)      // 73728
#define C2D (2*CD)          // 128
#define CK9 (C2D*9)         // 1152 = conv K

// ---------------------------------------------------------------------------
// Scratch (static device memory; no allocation at runtime)
// ---------------------------------------------------------------------------
__device__ float  g_xn[(size_t)CBT*C2D*CHW];        // conv input (bt,c,h,w)
__device__ float  g_xs_re[(size_t)CBT*CD*CHW];      // post-conv residual (bt,d,h,w)
__device__ float  g_xs_im[(size_t)CBT*CD*CHW];
__device__ float2 g_xeig[(size_t)NPIX*CD];          // (pix,d) complex; reused as delta
__device__ float2 g_xc[(size_t)NPIX*CD];            // decoded + LN'd (pix,d)
__device__ float2 g_act[(size_t)NPIX*CE*CF];        // MLP hidden (pix, e*F+f)
__device__ float  g_gates[(size_t)NPIX*CE];
__device__ float2 g_mpart[(size_t)CBT*12*CD];
__device__ float2 g_xmean[CB*CT*CD];
__device__ float  g_gatec[CB*CT*CD];
__device__ float2 g_srcc[CB*CT*CD];
__device__ float2 g_decc[CB*CT*CD];
__device__ float2 g_opfc[CB*CT*CD];

__device__ __forceinline__ float2 cmul(float2 a, float2 b) {
    return make_float2(a.x*b.x - a.y*b.y, a.x*b.y + a.y*b.x);
}
__device__ __forceinline__ float geluf(float x) {
    float x3 = x*x*x;
    return 0.5f*x*(1.0f + tanhf(0.7978845608028654f*(x + 0.044715f*x3)));
}
__device__ __forceinline__ uint32_t f2tf(float f) {
    uint32_t u; asm("cvt.rna.tf32.f32 %0, %1;" : "=r"(u) : "f"(f)); return u;
}

#define MMA_TF32(d, a, b0, b1) \
  asm volatile("mma.sync.aligned.m16n8k8.row.col.f32.tf32.tf32.f32 " \
    "{%0,%1,%2,%3}, {%4,%5,%6,%7}, {%8,%9}, {%0,%1,%2,%3};" \
    : "+f"((d)[0]),"+f"((d)[1]),"+f"((d)[2]),"+f"((d)[3]) \
    : "r"((a)[0]),"r"((a)[1]),"r"((a)[2]),"r"((a)[3]), "r"(b0),"r"(b1))

// ---------------------------------------------------------------------------
// K1: spatial LayerNorm over 128 channels ([re;im]) + metric -> g_xn
// ---------------------------------------------------------------------------
__global__ void k_ln_spatial(const float* __restrict__ xre, const float* __restrict__ xim,
                             const float* __restrict__ w, const float* __restrict__ b,
                             const float* __restrict__ metric)
{
    int pix = blockIdx.x*blockDim.x + threadIdx.x;
    if (pix >= NPIX) return;
    int bt = pix / CHW, hw = pix % CHW;
    size_t base = (size_t)bt*CD*CHW + hw;
    float s = 0.f, ss = 0.f;
    #pragma unroll 4
    for (int c = 0; c < C2D; c++) {
        float v = (c < CD) ? xre[base + (size_t)c*CHW] : xim[base + (size_t)(c-CD)*CHW];
        s += v; ss += v*v;
    }
    float mean = s * (1.f/128.f);
    float var  = ss * (1.f/128.f) - mean*mean;
    float inv  = rsqrtf(var + 1e-5f);
    float met  = metric[hw];
    size_t obase = (size_t)bt*C2D*CHW + hw;
    #pragma unroll 4
    for (int c = 0; c < C2D; c++) {
        float v = (c < CD) ? xre[base + (size_t)c*CHW] : xim[base + (size_t)(c-CD)*CHW];
        g_xn[obase + (size_t)c*CHW] = ((v - mean)*inv*w[c] + b[c]) * met;
    }
}

// ---------------------------------------------------------------------------
// K2: 3x3 conv 128->128 as implicit GEMM on tf32 tensor cores.
// Block: M=128 pixels (contiguous hw) x N=128 oc, K=1152 (ic*9), chunks of 32.
// im2col happens in the global->smem A staging (bounds-checked, m-fast).
// As layout [k][m] padded 136 (stride%32==8): conflict-free STS + frag LDS.
// Bs layout [n][k] padded 36: float4 k-fast loads, STS.128, frag reads 8*? ok.
// Epilogue: + bias + complex residual -> g_xs_re / g_xs_im (planar).
// ---------------------------------------------------------------------------
__global__ void k_conv_mma(const float* __restrict__ cw, const float* __restrict__ cb,
                           const float* __restrict__ xre, const float* __restrict__ xim)
{
    __shared__ uint32_t As[32][136];
    __shared__ uint32_t Bs[128][36];
    int mb = blockIdx.x;                  // 576 blocks
    int bt = mb / 18;
    int hwb = (mb % 18) * 128;
    int tid = threadIdx.x;
    int wid = tid >> 5, lane = tid & 31;
    int wm = wid & 3, wn = wid >> 2;      // 4 m-warps(32) x 2 n-warps(64)

    float acc[2][8][4];
    #pragma unroll
    for (int i = 0; i < 2; i++)
        #pragma unroll
        for (int j = 0; j < 8; j++)
            #pragma unroll
            for (int q = 0; q < 4; q++) acc[i][j][q] = 0.f;

    const float* xnb = g_xn + (size_t)bt*C2D*CHW;

    for (int c0 = 0; c0 < CK9; c0 += 32) {
        // --- A: im2col 128m x 32k, m-fast (coalesced along x) ---
        #pragma unroll
        for (int t = 0; t < 16; t++) {
            int lin = tid + t*256;
            int m = lin & 127, k = lin >> 7;
            int kk = c0 + k;
            int ic = kk / 9, tap = kk - ic*9;
            int ky = tap / 3, kx = tap - ky*3;
            int hw = hwb + m;
            int y = hw / CW + ky - 1;
            int x = hw % CW + kx - 1;
            float v = 0.f;
            if (y >= 0 && y < CH && x >= 0 && x < CW)
                v = xnb[((size_t)ic*CH + y)*CW + x];
            As[k][m] = f2tf(v);
        }
        // --- B: weights 128n x 32k, float4 k-fast loads ---
        #pragma unroll
        for (int t = 0; t < 4; t++) {
            int lin = tid + t*256;
            int n = lin >> 3, kq = (lin & 7)*4;
            float4 v = *reinterpret_cast<const float4*>(cw + (size_t)n*CK9 + c0 + kq);
            Bs[n][kq  ] = f2tf(v.x);
            Bs[n][kq+1] = f2tf(v.y);
            Bs[n][kq+2] = f2tf(v.z);
            Bs[n][kq+3] = f2tf(v.w);
        }
        __syncthreads();
        // --- mma: 4 k-steps of 8 ---
        #pragma unroll
        for (int ks = 0; ks < 4; ks++) {
            int kc = ks*8 + (lane & 3);
            uint32_t a[2][4];
            #pragma unroll
            for (int i = 0; i < 2; i++) {
                int r = wm*32 + i*16 + (lane >> 2);
                a[i][0] = As[kc  ][r];   a[i][1] = As[kc  ][r+8];
                a[i][2] = As[kc+4][r];   a[i][3] = As[kc+4][r+8];
            }
            #pragma unroll
            for (int j = 0; j < 8; j++) {
                int n0 = wn*64 + j*8 + (lane >> 2);
                int kb = ks*8 + (lane & 3);
                uint32_t b0 = Bs[n0][kb], b1 = Bs[n0][kb+4];
                #pragma unroll
                for (int i = 0; i < 2; i++)
                    MMA_TF32(acc[i][j], a[i], b0, b1);
            }
        }
        __syncthreads();
    }
    // --- epilogue: bias + residual -> planar g_xs ---
    #pragma unroll
    for (int i = 0; i < 2; i++) {
        int rbase = wm*32 + i*16 + (lane >> 2);
        #pragma unroll
        for (int j = 0; j < 8; j++) {
            int oc = wn*64 + j*8 + 2*(lane & 3);
            float b0 = cb[oc], b1 = cb[oc+1];
            #pragma unroll
            for (int h = 0; h < 2; h++) {
                int hw = hwb + rbase + h*8;
                float v0 = acc[i][j][h*2+0] + b0;
                float v1 = acc[i][j][h*2+1] + b1;
                if (oc < CD) {
                    size_t i0 = ((size_t)(bt*CD + oc  ))*CHW + hw;
                    size_t i1 = ((size_t)(bt*CD + oc+1))*CHW + hw;
                    g_xs_re[i0] = xre[i0] + v0;
                    g_xs_re[i1] = xre[i1] + v1;
                } else {
                    size_t i0 = ((size_t)(bt*CD + oc-CD  ))*CHW + hw;
                    size_t i1 = ((size_t)(bt*CD + oc-CD+1))*CHW + hw;
                    g_xs_im[i0] = xim[i0] + v0;
                    g_xs_im[i1] = xim[i1] + v1;
                }
            }
        }
    }
}

// ---------------------------------------------------------------------------
// Complex GEMM on tensor cores (tf32 mma.sync m16n8k8).
// C[m,n] = sum_k A[m,k]*B[k,n] (complex), via doubled-K real GEMMs:
//   C_re = A_rl @ [Br; -Bi],  C_im = A_rl @ [Bi; Br]
// ALAY: 0 = interleaved float2 A; 1 = planar (g_xs geometry)
// EPI : 0 = none; 1 = gelu(re/im) * gates[m*4 + z]
// ---------------------------------------------------------------------------
template<int ALAY, int EPI>
__global__ void k_mma(const float* __restrict__ A,
                      const float* __restrict__ Apre, const float* __restrict__ Apim,
                      const float* __restrict__ Bre, const float* __restrict__ Bim,
                      float2* __restrict__ C,
                      const float* __restrict__ gates,
                      int Kc, int ldaF, int ldb, int ldc, int zBoff, int zCoff)
{
    __shared__ uint32_t As[128][36];       // padded: bank-conflict-free frag reads
    __shared__ uint32_t Bs[2][32][68];     // [reC/imC][k_real][n]
    const int bm = blockIdx.y * 128;
    const int bn = blockIdx.x * 64;
    const int z  = blockIdx.z;
    Bre += (size_t)z * zBoff; Bim += (size_t)z * zBoff;
    C   += (size_t)z * zCoff;

    int tid = threadIdx.x;
    int wid = tid >> 5, lane = tid & 31;
    int wm = wid & 3, wn = wid >> 2;       // 4 m-warps x 2 n-warps

    int bt = 0, hwb = 0;
    if (ALAY == 1) { bt = bm / CHW; hwb = bm % CHW; }

    float acc[2][4][8];                    // [m-sub][n-sub][re0..3, im0..3]
    #pragma unroll
    for (int i = 0; i < 2; i++)
        #pragma unroll
        for (int j = 0; j < 4; j++)
            #pragma unroll
            for (int q = 0; q < 8; q++) acc[i][j][q] = 0.f;

    const int KR = 2*Kc;
    for (int c0 = 0; c0 < KR; c0 += 32) {
        // --- load A tile (128 x 32 reals) ---
        if (ALAY == 0) {
            #pragma unroll
            for (int t = 0; t < 16; t++) {
                int lin = tid + t*256;
                int m = lin >> 5, k = lin & 31;          // k-fast: coalesced
                As[m][k] = f2tf(A[(size_t)(bm + m)*ldaF + c0 + k]);
            }
        } else {
            #pragma unroll
            for (int t = 0; t < 16; t++) {
                int lin = tid + t*256;
                int m = lin & 127, k = lin >> 7;         // m-fast: coalesced planar
                int g = c0 + k, d = g >> 1;
                const float* P = (g & 1) ? Apim : Apre;
                As[m][k] = f2tf(P[(size_t)(bt*CD + d)*CHW + hwb + m]);
            }
        }
        // --- load combined B tiles (2 x 32 x 64) ---
        #pragma unroll
        for (int t = 0; t < 16; t++) {
            int lin = tid + t*256;
            int n = lin & 63, k = (lin >> 6) & 31, s = lin >> 11;
            int g = c0 + k, d = g >> 1, par = g & 1;
            size_t gi = (size_t)d*ldb + bn + n;
            float v;
            if (s == 0) v = par ? -Bim[gi] : Bre[gi];
            else        v = par ?  Bre[gi] : Bim[gi];
            Bs[s][k][n] = f2tf(v);
        }
        __syncthreads();
        // --- mma over 4 k-steps of 8 ---
        #pragma unroll
        for (int ks = 0; ks < 4; ks++) {
            int kc = ks*8 + (lane & 3);
            uint32_t a[2][4];
            #pragma unroll
            for (int i = 0; i < 2; i++) {
                int r = wm*32 + i*16 + (lane >> 2);
                a[i][0] = As[r  ][kc];   a[i][1] = As[r+8][kc];
                a[i][2] = As[r  ][kc+4]; a[i][3] = As[r+8][kc+4];
            }
            #pragma unroll
            for (int j = 0; j < 4; j++) {
                int n0 = wn*32 + j*8 + (lane >> 2);
                int kb = ks*8 + (lane & 3);
                uint32_t br0 = Bs[0][kb][n0], br1 = Bs[0][kb+4][n0];
                uint32_t bi0 = Bs[1][kb][n0], bi1 = Bs[1][kb+4][n0];
                #pragma unroll
                for (int i = 0; i < 2; i++) {
                    MMA_TF32(acc[i][j],     a[i], br0, br1);
                    MMA_TF32(acc[i][j] + 4, a[i], bi0, bi1);
                }
            }
        }
        __syncthreads();
    }
    // --- epilogue ---
    #pragma unroll
    for (int i = 0; i < 2; i++) {
        #pragma unroll
        for (int j = 0; j < 4; j++) {
            int rbase = bm + wm*32 + i*16 + (lane >> 2);
            int cbase = bn + wn*32 + j*8 + 2*(lane & 3);
            #pragma unroll
            for (int h = 0; h < 2; h++) {                // c0/c1 then c2/c3 (+8 rows)
                int m = rbase + h*8;
                float re0 = acc[i][j][h*2+0], re1 = acc[i][j][h*2+1];
                float im0 = acc[i][j][h*2+4], im1 = acc[i][j][h*2+5];
                if (EPI == 1) {
                    float g = gates[(size_t)m*CE + z];
                    re0 = geluf(re0)*g; im0 = geluf(im0)*g;
                    re1 = geluf(re1)*g; im1 = geluf(im1)*g;
                }
                float4 v = make_float4(re0, im0, re1, im1);
                *reinterpret_cast<float4*>(&C[(size_t)m*ldc + cbase]) = v;
            }
        }
    }
}

// ---------------------------------------------------------------------------
// K4: partial mean over H*W  (x_eig -> g_mpart), final reduce in k_scan
// ---------------------------------------------------------------------------
__global__ void k_mean_part()
{
    int bt = blockIdx.x, sl = blockIdx.y;
    int tid = threadIdx.x, d = tid & 63, grp = tid >> 6;
    float2 acc = make_float2(0.f, 0.f);
    #pragma unroll 4
    for (int it = 0; it < 48; it++) {
        int hw = sl*192 + it*4 + grp;
        float2 v = g_xeig[(size_t)(bt*CHW + hw)*CD + d];
        acc.x += v.x; acc.y += v.y;
    }
    __shared__ float2 red[256];
    red[tid] = acc;
    __syncthreads();
    if (tid < 64) {
        float2 t = red[tid];
        t.x += red[tid+64].x + red[tid+128].x + red[tid+192].x;
        t.y += red[tid+64].y + red[tid+128].y + red[tid+192].y;
        g_mpart[(size_t)(bt*12 + sl)*CD + tid] = t;
    }
}

// ---------------------------------------------------------------------------
// K5: mean finalize + flux scan + lambda / decay / forcing coefficients
// ---------------------------------------------------------------------------
__global__ void k_scan(const float* __restrict__ dt,
                       const float* __restrict__ fpre, const float* __restrict__ fpim,
                       const float* __restrict__ Wg, const float* __restrict__ bg,
                       const float* __restrict__ are, const float* __restrict__ aim,
                       const float* __restrict__ lnu, const float* __restrict__ limv)
{
    int tid = threadIdx.x;
    if (tid >= CB*CD) return;
    int b = tid >> 6, d = tid & 63;
    for (int t = 0; t < CT; t++) {
        int bt = b*CT + t;
        float2 s = make_float2(0.f, 0.f);
        #pragma unroll
        for (int sl = 0; sl < 12; sl++) {
            float2 v = g_mpart[(size_t)(bt*12 + sl)*CD + d];
            s.x += v.x; s.y += v.y;
        }
        g_xmean[bt*CD + d] = make_float2(s.x * (1.f/CHW), s.y * (1.f/CHW));
    }
    __syncthreads();
    float x = lnu[d];
    float sp = (x > 20.f) ? x : log1pf(expf(x));
    float lre = -sp - 1e-4f;
    float lim = limv[d];
    float den = lre*lre + lim*lim;
    float2 alpha = make_float2(are[d], aim[d]);
    float2 flux  = make_float2(fpre[b*CD + d], fpim[b*CD + d]);
    for (int t = 0; t < CT; t++) {
        int base = (b*CT + t)*CD;
        float s = bg[d];
        for (int k = 0; k < CD; k++)
            s = fmaf(g_xmean[base + k].x, Wg[k*CD + d], s);
        float g = 1.f / (1.f + expf(-s));
        float2 xm = g_xmean[base + d];
        float2 nf = make_float2(flux.x*g + xm.x*(1.f - g), flux.y*g + xm.y*(1.f - g));
        flux = nf;
        float2 src = cmul(nf, alpha);
        float dtv = dt[t];
        float er = expf(lre*dtv), ph = lim*dtv;
        float2 dec = make_float2(er*cosf(ph), er*sinf(ph));
        float nr = dec.x - 1.f, ni = dec.y;
        float2 opf = make_float2((nr*lre + ni*lim)/den, (ni*lre - nr*lim)/den);
        int idx = base + d;
        g_gatec[idx] = g; g_srcc[idx] = src; g_decc[idx] = dec; g_opfc[idx] = opf;
    }
}

// ---------------------------------------------------------------------------
// K6: forcing + temporal associative scan + h_prev term (in-place on g_xeig)
// ---------------------------------------------------------------------------
__global__ void k_temporal(const float* __restrict__ hre, const float* __restrict__ him)
{
    int idx = blockIdx.x*blockDim.x + threadIdx.x;     // (b,hw,d)
    if (idx >= CB*CHW*CD) return;
    int d = idx & 63;
    int hw = (idx >> 6) % CHW;
    int b = idx / (CHW*CD);
    float2 hp = make_float2(hre[idx], him[idx]);
    float2 y = make_float2(0.f, 0.f);
    for (int t = 0; t < CT; t++) {
        int ci = (b*CT + t)*CD + d;
        float g = g_gatec[ci];
        float2 src = g_srcc[ci], dec = g_decc[ci], opf = g_opfc[ci];
        size_t ei = (size_t)((b*CT + t)*CHW + hw)*CD + d;
        float2 xe = g_xeig[ei];
        float2 f = make_float2(xe.x*g + src.x*(1.f - g), xe.y*g + src.y*(1.f - g));
        float2 ut = cmul(f, opf);
        float2 yn = cmul(dec, y);
        y = make_float2(yn.x + ut.x, yn.y + ut.y);
        float2 hd = cmul(hp, dec);
        g_xeig[ei] = make_float2(y.x + hd.x, y.y + hd.y);
    }
}

// ---------------------------------------------------------------------------
// K8: temporal LayerNorm (in-place on g_xc) + softmax gates — warp per pixel
// ---------------------------------------------------------------------------
__global__ void k_ln2gate(const float* __restrict__ w, const float* __restrict__ b,
                          const float* __restrict__ Wgate)
{
    int gwarp = (blockIdx.x*blockDim.x + threadIdx.x) >> 5;
    int lane = threadIdx.x & 31;
    if (gwarp >= NPIX) return;
    size_t base = (size_t)gwarp * CD;
    float2 v0 = g_xc[base + lane];
    float2 v1 = g_xc[base + 32 + lane];
    float s  = v0.x + v0.y + v1.x + v1.y;
    float ss = v0.x*v0.x + v0.y*v0.y + v1.x*v1.x + v1.y*v1.y;
    #pragma unroll
    for (int o = 16; o; o >>= 1) {
        s  += __shfl_xor_sync(0xffffffffu, s, o);
        ss += __shfl_xor_sync(0xffffffffu, ss, o);
    }
    float mean = s * (1.f/128.f);
    float var  = ss * (1.f/128.f) - mean*mean;
    float inv  = rsqrtf(var + 1e-5f);
    int d0 = lane, d1 = lane + 32;
    float xr0 = (v0.x - mean)*inv*w[d0]      + b[d0];
    float xi0 = (v0.y - mean)*inv*w[CD + d0] + b[CD + d0];
    float xr1 = (v1.x - mean)*inv*w[d1]      + b[d1];
    float xi1 = (v1.y - mean)*inv*w[CD + d1] + b[CD + d1];
    g_xc[base + d0] = make_float2(xr0, xi0);
    g_xc[base + d1] = make_float2(xr1, xi1);
    float pe[CE];
    #pragma unroll
    for (int e = 0; e < CE; e++)
        pe[e] = xr0*Wgate[d0*CE + e] + xr1*Wgate[d1*CE + e];
    #pragma unroll
    for (int e = 0; e < CE; e++)
        #pragma unroll
        for (int o = 16; o; o >>= 1)
            pe[e] += __shfl_xor_sync(0xffffffffu, pe[e], o);
    float m = fmaxf(fmaxf(pe[0], pe[1]), fmaxf(pe[2], pe[3]));
    float e0 = expf(pe[0]-m), e1 = expf(pe[1]-m), e2 = expf(pe[2]-m), e3 = expf(pe[3]-m);
    float denom = e0 + e1 + e2 + e3;
    if (lane == 0) {
        float* gp = &g_gates[(size_t)gwarp*CE];
        gp[0] = e0/denom; gp[1] = e1/denom; gp[2] = e2/denom; gp[3] = e3/denom;
    }
}

// ---------------------------------------------------------------------------
// K11: combine (xc + delta) transpose back to (bt,d,h,w) + residual -> out
// ---------------------------------------------------------------------------
__global__ void k_combine(float2* __restrict__ out)
{
    __shared__ float2 sm[32][65];
    int pix0 = blockIdx.x * 32;
    int bt = pix0 / CHW, hw0 = pix0 % CHW;
    int tid = threadIdx.x;
    #pragma unroll
    for (int i = 0; i < 8; i++) {
        int lin = tid + i*256;
        int p = lin >> 6, d = lin & 63;
        size_t gi = (size_t)(pix0 + p)*CD + d;
        float2 v  = g_xc[gi];
        float2 dl = g_xeig[gi];
        sm[p][d] = make_float2(v.x + dl.x, v.y + dl.y);
    }
    __syncthreads();
    #pragma unroll
    for (int i = 0; i < 8; i++) {
        int lin = tid + i*256;
        int p = lin & 31, d = lin >> 5;
        size_t gi = (size_t)(bt*CD + d)*CHW + hw0 + p;
        float2 v = sm[p][d];
        out[gi] = make_float2(g_xs_re[gi] + v.x, g_xs_im[gi] + v.y);
    }
}

// ---------------------------------------------------------------------------
// Host launcher
// ---------------------------------------------------------------------------
extern "C" void kernel_launch(void* const* d_in, const int* in_sizes, int n_in,
                              void* d_out, int out_size)
{
    const float* x_re   = (const float*)d_in[0];
    const float* x_im   = (const float*)d_in[1];
    const float* hp_re  = (const float*)d_in[2];
    const float* hp_im  = (const float*)d_in[3];
    const float* dt     = (const float*)d_in[4];
    const float* fp_re  = (const float*)d_in[5];
    const float* fp_im  = (const float*)d_in[6];
    const float* lnsp_w = (const float*)d_in[7];
    const float* lnsp_b = (const float*)d_in[8];
    const float* conv_w = (const float*)d_in[9];
    const float* conv_b = (const float*)d_in[10];
    const float* metric = (const float*)d_in[11];
    const float* lnt_w  = (const float*)d_in[12];
    const float* lnt_b  = (const float*)d_in[13];
    const float* Eenc_r = (const float*)d_in[14];
    const float* Eenc_i = (const float*)d_in[15];
    const float* Edec_r = (const float*)d_in[16];
    const float* Edec_i = (const float*)d_in[17];
    const float* Wg     = (const float*)d_in[18];
    const float* bg     = (const float*)d_in[19];
    const float* al_re  = (const float*)d_in[20];
    const float* al_im  = (const float*)d_in[21];
    const float* lam_nu = (const float*)d_in[22];
    const float* lam_im = (const float*)d_in[23];
    const float* Wgate  = (const float*)d_in[24];
    const float* W1_re  = (const float*)d_in[25];
    const float* W1_im  = (const float*)d_in[26];
    const float* W2_re  = (const float*)d_in[27];
    const float* W2_im  = (const float*)d_in[28];

    float2 *p_xeig = 0, *p_xc = 0, *p_act = 0;
    float  *p_xsre = 0, *p_xsim = 0, *p_gates = 0;
    cudaGetSymbolAddress((void**)&p_xeig,  g_xeig);
    cudaGetSymbolAddress((void**)&p_xc,    g_xc);
    cudaGetSymbolAddress((void**)&p_act,   g_act);
    cudaGetSymbolAddress((void**)&p_xsre,  g_xs_re);
    cudaGetSymbolAddress((void**)&p_xsim,  g_xs_im);
    cudaGetSymbolAddress((void**)&p_gates, g_gates);

    // 1. spatial LN + metric
    k_ln_spatial<<<(NPIX + 255)/256, 256>>>(x_re, x_im, lnsp_w, lnsp_b, metric);

    // 2. conv 3x3 as implicit GEMM on tensor cores
    k_conv_mma<<<NPIX/128, 256>>>(conv_w, conv_b, x_re, x_im);

    // 3. x_eig = xs @ E_enc   (planar A, tensor cores)
    k_mma<1,0><<<dim3(1, NPIX/128, 1), 256>>>(
        nullptr, p_xsre, p_xsim, Eenc_r, Eenc_i, p_xeig, nullptr,
        CD, 0, CD, CD, 0, 0);

    // 4. partial mean over H*W
    k_mean_part<<<dim3(CBT, 12), 256>>>();

    // 5. mean finalize + flux scan + coefficients
    k_scan<<<1, 128>>>(dt, fp_re, fp_im, Wg, bg, al_re, al_im, lam_nu, lam_im);

    // 6. forcing + temporal scan + h_prev
    k_temporal<<<(CB*CHW*CD + 255)/256, 256>>>(hp_re, hp_im);

    // 7. xc_raw = u @ E_dec
    k_mma<0,0><<<dim3(1, NPIX/128, 1), 256>>>(
        (const float*)p_xeig, nullptr, nullptr, Edec_r, Edec_i, p_xc, nullptr,
        CD, 2*CD, CD, CD, 0, 0);

    // 8. temporal LN (in-place) + softmax gates
    k_ln2gate<<<NPIX/8, 256>>>(lnt_w, lnt_b, Wgate);

    // 9. h1 per e (gelu * gate epilogue) -> g_act (m, e*F+f)
    k_mma<0,1><<<dim3(CF/64, NPIX/128, CE), 256>>>(
        (const float*)p_xc, nullptr, nullptr, W1_re, W1_im, p_act, p_gates,
        CD, 2*CD, CF, CE*CF, CD*CF, CF);

    // 10. delta = a_scaled @ W2(viewed as (E*F, D)) -> g_xeig (reuse)
    k_mma<0,0><<<dim3(1, NPIX/128, 1), 256>>>(
        (const float*)p_act, nullptr, nullptr, W2_re, W2_im, p_xeig, nullptr,
        CE*CF, 2*CE*CF, CD, CD, 0, 0);

    // 11. combine + transpose + final residual -> out
    k_combine<<<NPIX/32, 256>>>((float2*)d_out);
}

// round 6
// speedup vs baseline: 1.3822x; 1.0011x over previous
#include <cuda_runtime.h>
#include <math.h>
#include <stdint.h>

// Problem constants
#define CB 2
#define CT 16
#define CD 64
#define CH 48
#define CW 48
#define CE 4
#define CF 128
#define CBT (CB*CT)         // 32
#define CHW (CH*CW)         // 2304
#define NPIX (CBT*CHW)      // 73728
#define C2D (2*CD)          // 128
#define CK9 (C2D*9)         // 1152 = conv K

// ---------------------------------------------------------------------------
// Scratch (static device memory; no allocation at runtime)
// ---------------------------------------------------------------------------
__device__ float  g_xn[(size_t)CBT*C2D*CHW];        // conv input (bt,c,h,w)
__device__ float  g_xs_re[(size_t)CBT*CD*CHW];      // post-conv residual (bt,d,h,w)
__device__ float  g_xs_im[(size_t)CBT*CD*CHW];
__device__ float2 g_xeig[(size_t)NPIX*CD];          // (pix,d) complex; reused as delta
__device__ float2 g_xc[(size_t)NPIX*CD];            // decoded + LN'd (pix,d)
__device__ float2 g_act[(size_t)NPIX*CE*CF];        // MLP hidden (pix, e*F+f)
__device__ float  g_gates[(size_t)NPIX*CE];
__device__ float2 g_mpart[(size_t)CBT*12*CD];
__device__ float2 g_xmean[CB*CT*CD];
__device__ float  g_gatec[CB*CT*CD];
__device__ float2 g_srcc[CB*CT*CD];
__device__ float2 g_decc[CB*CT*CD];
__device__ float2 g_opfc[CB*CT*CD];

__device__ __forceinline__ float2 cmul(float2 a, float2 b) {
    return make_float2(a.x*b.x - a.y*b.y, a.x*b.y + a.y*b.x);
}
__device__ __forceinline__ float geluf(float x) {
    float x3 = x*x*x;
    return 0.5f*x*(1.0f + tanhf(0.7978845608028654f*(x + 0.044715f*x3)));
}
__device__ __forceinline__ uint32_t f2tf(float f) {
    uint32_t u; asm("cvt.rna.tf32.f32 %0, %1;" : "=r"(u) : "f"(f)); return u;
}

#define MMA_TF32(d, a, b0, b1) \
  asm volatile("mma.sync.aligned.m16n8k8.row.col.f32.tf32.tf32.f32 " \
    "{%0,%1,%2,%3}, {%4,%5,%6,%7}, {%8,%9}, {%0,%1,%2,%3};" \
    : "+f"((d)[0]),"+f"((d)[1]),"+f"((d)[2]),"+f"((d)[3]) \
    : "r"((a)[0]),"r"((a)[1]),"r"((a)[2]),"r"((a)[3]), "r"(b0),"r"(b1))

// ---------------------------------------------------------------------------
// K1: spatial LayerNorm over 128 channels ([re;im]) + metric -> g_xn
// ---------------------------------------------------------------------------
__global__ void k_ln_spatial(const float* __restrict__ xre, const float* __restrict__ xim,
                             const float* __restrict__ w, const float* __restrict__ b,
                             const float* __restrict__ metric)
{
    int pix = blockIdx.x*blockDim.x + threadIdx.x;
    if (pix >= NPIX) return;
    int bt = pix / CHW, hw = pix % CHW;
    size_t base = (size_t)bt*CD*CHW + hw;
    float s = 0.f, ss = 0.f;
    #pragma unroll 4
    for (int c = 0; c < C2D; c++) {
        float v = (c < CD) ? xre[base + (size_t)c*CHW] : xim[base + (size_t)(c-CD)*CHW];
        s += v; ss += v*v;
    }
    float mean = s * (1.f/128.f);
    float var  = ss * (1.f/128.f) - mean*mean;
    float inv  = rsqrtf(var + 1e-5f);
    float met  = metric[hw];
    size_t obase = (size_t)bt*C2D*CHW + hw;
    #pragma unroll 4
    for (int c = 0; c < C2D; c++) {
        float v = (c < CD) ? xre[base + (size_t)c*CHW] : xim[base + (size_t)(c-CD)*CHW];
        g_xn[obase + (size_t)c*CHW] = ((v - mean)*inv*w[c] + b[c]) * met;
    }
}

// ---------------------------------------------------------------------------
// K2: 3x3 conv 128->128 as implicit GEMM on tf32 tensor cores.
// Block: M=128 pixels (contiguous hw) x N=128 oc, K=1152 (ic*9), chunks of 32.
// im2col happens in the global->smem A staging (bounds-checked, m-fast).
// As layout [k][m] padded 136 (stride%32==8): conflict-free STS + frag LDS.
// Bs layout [n][k] padded 36: float4 k-fast loads, STS.128, frag reads 8*? ok.
// Epilogue: + bias + complex residual -> g_xs_re / g_xs_im (planar).
// ---------------------------------------------------------------------------
__global__ void k_conv_mma(const float* __restrict__ cw, const float* __restrict__ cb,
                           const float* __restrict__ xre, const float* __restrict__ xim)
{
    __shared__ uint32_t As[32][136];
    __shared__ uint32_t Bs[128][36];
    int mb = blockIdx.x;                  // 576 blocks
    int bt = mb / 18;
    int hwb = (mb % 18) * 128;
    int tid = threadIdx.x;
    int wid = tid >> 5, lane = tid & 31;
    int wm = wid & 3, wn = wid >> 2;      // 4 m-warps(32) x 2 n-warps(64)

    float acc[2][8][4];
    #pragma unroll
    for (int i = 0; i < 2; i++)
        #pragma unroll
        for (int j = 0; j < 8; j++)
            #pragma unroll
            for (int q = 0; q < 4; q++) acc[i][j][q] = 0.f;

    const float* xnb = g_xn + (size_t)bt*C2D*CHW;

    for (int c0 = 0; c0 < CK9; c0 += 32) {
        // --- A: im2col 128m x 32k, m-fast (coalesced along x) ---
        #pragma unroll
        for (int t = 0; t < 16; t++) {
            int lin = tid + t*256;
            int m = lin & 127, k = lin >> 7;
            int kk = c0 + k;
            int ic = kk / 9, tap = kk - ic*9;
            int ky = tap / 3, kx = tap - ky*3;
            int hw = hwb + m;
            int y = hw / CW + ky - 1;
            int x = hw % CW + kx - 1;
            float v = 0.f;
            if (y >= 0 && y < CH && x >= 0 && x < CW)
                v = xnb[((size_t)ic*CH + y)*CW + x];
            As[k][m] = f2tf(v);
        }
        // --- B: weights 128n x 32k, float4 k-fast loads ---
        #pragma unroll
        for (int t = 0; t < 4; t++) {
            int lin = tid + t*256;
            int n = lin >> 3, kq = (lin & 7)*4;
            float4 v = *reinterpret_cast<const float4*>(cw + (size_t)n*CK9 + c0 + kq);
            Bs[n][kq  ] = f2tf(v.x);
            Bs[n][kq+1] = f2tf(v.y);
            Bs[n][kq+2] = f2tf(v.z);
            Bs[n][kq+3] = f2tf(v.w);
        }
        __syncthreads();
        // --- mma: 4 k-steps of 8 ---
        #pragma unroll
        for (int ks = 0; ks < 4; ks++) {
            int kc = ks*8 + (lane & 3);
            uint32_t a[2][4];
            #pragma unroll
            for (int i = 0; i < 2; i++) {
                int r = wm*32 + i*16 + (lane >> 2);
                a[i][0] = As[kc  ][r];   a[i][1] = As[kc  ][r+8];
                a[i][2] = As[kc+4][r];   a[i][3] = As[kc+4][r+8];
            }
            #pragma unroll
            for (int j = 0; j < 8; j++) {
                int n0 = wn*64 + j*8 + (lane >> 2);
                int kb = ks*8 + (lane & 3);
                uint32_t b0 = Bs[n0][kb], b1 = Bs[n0][kb+4];
                #pragma unroll
                for (int i = 0; i < 2; i++)
                    MMA_TF32(acc[i][j], a[i], b0, b1);
            }
        }
        __syncthreads();
    }
    // --- epilogue: bias + residual -> planar g_xs ---
    #pragma unroll
    for (int i = 0; i < 2; i++) {
        int rbase = wm*32 + i*16 + (lane >> 2);
        #pragma unroll
        for (int j = 0; j < 8; j++) {
            int oc = wn*64 + j*8 + 2*(lane & 3);
            float b0 = cb[oc], b1 = cb[oc+1];
            #pragma unroll
            for (int h = 0; h < 2; h++) {
                int hw = hwb + rbase + h*8;
                float v0 = acc[i][j][h*2+0] + b0;
                float v1 = acc[i][j][h*2+1] + b1;
                if (oc < CD) {
                    size_t i0 = ((size_t)(bt*CD + oc  ))*CHW + hw;
                    size_t i1 = ((size_t)(bt*CD + oc+1))*CHW + hw;
                    g_xs_re[i0] = xre[i0] + v0;
                    g_xs_re[i1] = xre[i1] + v1;
                } else {
                    size_t i0 = ((size_t)(bt*CD + oc-CD  ))*CHW + hw;
                    size_t i1 = ((size_t)(bt*CD + oc-CD+1))*CHW + hw;
                    g_xs_im[i0] = xim[i0] + v0;
                    g_xs_im[i1] = xim[i1] + v1;
                }
            }
        }
    }
}

// ---------------------------------------------------------------------------
// Complex GEMM on tensor cores (tf32 mma.sync m16n8k8).
// C[m,n] = sum_k A[m,k]*B[k,n] (complex), via doubled-K real GEMMs:
//   C_re = A_rl @ [Br; -Bi],  C_im = A_rl @ [Bi; Br]
// ALAY: 0 = interleaved float2 A; 1 = planar (g_xs geometry)
// EPI : 0 = none; 1 = gelu(re/im) * gates[m*4 + z]
// ---------------------------------------------------------------------------
template<int ALAY, int EPI>
__global__ void k_mma(const float* __restrict__ A,
                      const float* __restrict__ Apre, const float* __restrict__ Apim,
                      const float* __restrict__ Bre, const float* __restrict__ Bim,
                      float2* __restrict__ C,
                      const float* __restrict__ gates,
                      int Kc, int ldaF, int ldb, int ldc, int zBoff, int zCoff)
{
    __shared__ uint32_t As[128][36];       // padded: bank-conflict-free frag reads
    __shared__ uint32_t Bs[2][32][68];     // [reC/imC][k_real][n]
    const int bm = blockIdx.y * 128;
    const int bn = blockIdx.x * 64;
    const int z  = blockIdx.z;
    Bre += (size_t)z * zBoff; Bim += (size_t)z * zBoff;
    C   += (size_t)z * zCoff;

    int tid = threadIdx.x;
    int wid = tid >> 5, lane = tid & 31;
    int wm = wid & 3, wn = wid >> 2;       // 4 m-warps x 2 n-warps

    int bt = 0, hwb = 0;
    if (ALAY == 1) { bt = bm / CHW; hwb = bm % CHW; }

    float acc[2][4][8];                    // [m-sub][n-sub][re0..3, im0..3]
    #pragma unroll
    for (int i = 0; i < 2; i++)
        #pragma unroll
        for (int j = 0; j < 4; j++)
            #pragma unroll
            for (int q = 0; q < 8; q++) acc[i][j][q] = 0.f;

    const int KR = 2*Kc;
    for (int c0 = 0; c0 < KR; c0 += 32) {
        // --- load A tile (128 x 32 reals) ---
        if (ALAY == 0) {
            #pragma unroll
            for (int t = 0; t < 16; t++) {
                int lin = tid + t*256;
                int m = lin >> 5, k = lin & 31;          // k-fast: coalesced
                As[m][k] = f2tf(A[(size_t)(bm + m)*ldaF + c0 + k]);
            }
        } else {
            #pragma unroll
            for (int t = 0; t < 16; t++) {
                int lin = tid + t*256;
                int m = lin & 127, k = lin >> 7;         // m-fast: coalesced planar
                int g = c0 + k, d = g >> 1;
                const float* P = (g & 1) ? Apim : Apre;
                As[m][k] = f2tf(P[(size_t)(bt*CD + d)*CHW + hwb + m]);
            }
        }
        // --- load combined B tiles (2 x 32 x 64) ---
        #pragma unroll
        for (int t = 0; t < 16; t++) {
            int lin = tid + t*256;
            int n = lin & 63, k = (lin >> 6) & 31, s = lin >> 11;
            int g = c0 + k, d = g >> 1, par = g & 1;
            size_t gi = (size_t)d*ldb + bn + n;
            float v;
            if (s == 0) v = par ? -Bim[gi] : Bre[gi];
            else        v = par ?  Bre[gi] : Bim[gi];
            Bs[s][k][n] = f2tf(v);
        }
        __syncthreads();
        // --- mma over 4 k-steps of 8 ---
        #pragma unroll
        for (int ks = 0; ks < 4; ks++) {
            int kc = ks*8 + (lane & 3);
            uint32_t a[2][4];
            #pragma unroll
            for (int i = 0; i < 2; i++) {
                int r = wm*32 + i*16 + (lane >> 2);
                a[i][0] = As[r  ][kc];   a[i][1] = As[r+8][kc];
                a[i][2] = As[r  ][kc+4]; a[i][3] = As[r+8][kc+4];
            }
            #pragma unroll
            for (int j = 0; j < 4; j++) {
                int n0 = wn*32 + j*8 + (lane >> 2);
                int kb = ks*8 + (lane & 3);
                uint32_t br0 = Bs[0][kb][n0], br1 = Bs[0][kb+4][n0];
                uint32_t bi0 = Bs[1][kb][n0], bi1 = Bs[1][kb+4][n0];
                #pragma unroll
                for (int i = 0; i < 2; i++) {
                    MMA_TF32(acc[i][j],     a[i], br0, br1);
                    MMA_TF32(acc[i][j] + 4, a[i], bi0, bi1);
                }
            }
        }
        __syncthreads();
    }
    // --- epilogue ---
    #pragma unroll
    for (int i = 0; i < 2; i++) {
        #pragma unroll
        for (int j = 0; j < 4; j++) {
            int rbase = bm + wm*32 + i*16 + (lane >> 2);
            int cbase = bn + wn*32 + j*8 + 2*(lane & 3);
            #pragma unroll
            for (int h = 0; h < 2; h++) {                // c0/c1 then c2/c3 (+8 rows)
                int m = rbase + h*8;
                float re0 = acc[i][j][h*2+0], re1 = acc[i][j][h*2+1];
                float im0 = acc[i][j][h*2+4], im1 = acc[i][j][h*2+5];
                if (EPI == 1) {
                    float g = gates[(size_t)m*CE + z];
                    re0 = geluf(re0)*g; im0 = geluf(im0)*g;
                    re1 = geluf(re1)*g; im1 = geluf(im1)*g;
                }
                float4 v = make_float4(re0, im0, re1, im1);
                *reinterpret_cast<float4*>(&C[(size_t)m*ldc + cbase]) = v;
            }
        }
    }
}

// ---------------------------------------------------------------------------
// K4: partial mean over H*W  (x_eig -> g_mpart), final reduce in k_scan
// ---------------------------------------------------------------------------
__global__ void k_mean_part()
{
    int bt = blockIdx.x, sl = blockIdx.y;
    int tid = threadIdx.x, d = tid & 63, grp = tid >> 6;
    float2 acc = make_float2(0.f, 0.f);
    #pragma unroll 4
    for (int it = 0; it < 48; it++) {
        int hw = sl*192 + it*4 + grp;
        float2 v = g_xeig[(size_t)(bt*CHW + hw)*CD + d];
        acc.x += v.x; acc.y += v.y;
    }
    __shared__ float2 red[256];
    red[tid] = acc;
    __syncthreads();
    if (tid < 64) {
        float2 t = red[tid];
        t.x += red[tid+64].x + red[tid+128].x + red[tid+192].x;
        t.y += red[tid+64].y + red[tid+128].y + red[tid+192].y;
        g_mpart[(size_t)(bt*12 + sl)*CD + tid] = t;
    }
}

// ---------------------------------------------------------------------------
// K5: mean finalize + flux scan + lambda / decay / forcing coefficients
// ---------------------------------------------------------------------------
__global__ void k_scan(const float* __restrict__ dt,
                       const float* __restrict__ fpre, const float* __restrict__ fpim,
                       const float* __restrict__ Wg, const float* __restrict__ bg,
                       const float* __restrict__ are, const float* __restrict__ aim,
                       const float* __restrict__ lnu, const float* __restrict__ limv)
{
    int tid = threadIdx.x;
    if (tid >= CB*CD) return;
    int b = tid >> 6, d = tid & 63;
    for (int t = 0; t < CT; t++) {
        int bt = b*CT + t;
        float2 s = make_float2(0.f, 0.f);
        #pragma unroll
        for (int sl = 0; sl < 12; sl++) {
            float2 v = g_mpart[(size_t)(bt*12 + sl)*CD + d];
            s.x += v.x; s.y += v.y;
        }
        g_xmean[bt*CD + d] = make_float2(s.x * (1.f/CHW), s.y * (1.f/CHW));
    }
    __syncthreads();
    float x = lnu[d];
    float sp = (x > 20.f) ? x : log1pf(expf(x));
    float lre = -sp - 1e-4f;
    float lim = limv[d];
    float den = lre*lre + lim*lim;
    float2 alpha = make_float2(are[d], aim[d]);
    float2 flux  = make_float2(fpre[b*CD + d], fpim[b*CD + d]);
    for (int t = 0; t < CT; t++) {
        int base = (b*CT + t)*CD;
        float s = bg[d];
        for (int k = 0; k < CD; k++)
            s = fmaf(g_xmean[base + k].x, Wg[k*CD + d], s);
        float g = 1.f / (1.f + expf(-s));
        float2 xm = g_xmean[base + d];
        float2 nf = make_float2(flux.x*g + xm.x*(1.f - g), flux.y*g + xm.y*(1.f - g));
        flux = nf;
        float2 src = cmul(nf, alpha);
        float dtv = dt[t];
        float er = expf(lre*dtv), ph = lim*dtv;
        float2 dec = make_float2(er*cosf(ph), er*sinf(ph));
        float nr = dec.x - 1.f, ni = dec.y;
        float2 opf = make_float2((nr*lre + ni*lim)/den, (ni*lre - nr*lim)/den);
        int idx = base + d;
        g_gatec[idx] = g; g_srcc[idx] = src; g_decc[idx] = dec; g_opfc[idx] = opf;
    }
}

// ---------------------------------------------------------------------------
// K6: forcing + temporal associative scan + h_prev term (in-place on g_xeig)
// ---------------------------------------------------------------------------
__global__ void k_temporal(const float* __restrict__ hre, const float* __restrict__ him)
{
    int idx = blockIdx.x*blockDim.x + threadIdx.x;     // (b,hw,d)
    if (idx >= CB*CHW*CD) return;
    int d = idx & 63;
    int hw = (idx >> 6) % CHW;
    int b = idx / (CHW*CD);
    float2 hp = make_float2(hre[idx], him[idx]);
    float2 y = make_float2(0.f, 0.f);
    for (int t = 0; t < CT; t++) {
        int ci = (b*CT + t)*CD + d;
        float g = g_gatec[ci];
        float2 src = g_srcc[ci], dec = g_decc[ci], opf = g_opfc[ci];
        size_t ei = (size_t)((b*CT + t)*CHW + hw)*CD + d;
        float2 xe = g_xeig[ei];
        float2 f = make_float2(xe.x*g + src.x*(1.f - g), xe.y*g + src.y*(1.f - g));
        float2 ut = cmul(f, opf);
        float2 yn = cmul(dec, y);
        y = make_float2(yn.x + ut.x, yn.y + ut.y);
        float2 hd = cmul(hp, dec);
        g_xeig[ei] = make_float2(y.x + hd.x, y.y + hd.y);
    }
}

// ---------------------------------------------------------------------------
// K8: temporal LayerNorm (in-place on g_xc) + softmax gates — warp per pixel
// ---------------------------------------------------------------------------
__global__ void k_ln2gate(const float* __restrict__ w, const float* __restrict__ b,
                          const float* __restrict__ Wgate)
{
    int gwarp = (blockIdx.x*blockDim.x + threadIdx.x) >> 5;
    int lane = threadIdx.x & 31;
    if (gwarp >= NPIX) return;
    size_t base = (size_t)gwarp * CD;
    float2 v0 = g_xc[base + lane];
    float2 v1 = g_xc[base + 32 + lane];
    float s  = v0.x + v0.y + v1.x + v1.y;
    float ss = v0.x*v0.x + v0.y*v0.y + v1.x*v1.x + v1.y*v1.y;
    #pragma unroll
    for (int o = 16; o; o >>= 1) {
        s  += __shfl_xor_sync(0xffffffffu, s, o);
        ss += __shfl_xor_sync(0xffffffffu, ss, o);
    }
    float mean = s * (1.f/128.f);
    float var  = ss * (1.f/128.f) - mean*mean;
    float inv  = rsqrtf(var + 1e-5f);
    int d0 = lane, d1 = lane + 32;
    float xr0 = (v0.x - mean)*inv*w[d0]      + b[d0];
    float xi0 = (v0.y - mean)*inv*w[CD + d0] + b[CD + d0];
    float xr1 = (v1.x - mean)*inv*w[d1]      + b[d1];
    float xi1 = (v1.y - mean)*inv*w[CD + d1] + b[CD + d1];
    g_xc[base + d0] = make_float2(xr0, xi0);
    g_xc[base + d1] = make_float2(xr1, xi1);
    float pe[CE];
    #pragma unroll
    for (int e = 0; e < CE; e++)
        pe[e] = xr0*Wgate[d0*CE + e] + xr1*Wgate[d1*CE + e];
    #pragma unroll
    for (int e = 0; e < CE; e++)
        #pragma unroll
        for (int o = 16; o; o >>= 1)
            pe[e] += __shfl_xor_sync(0xffffffffu, pe[e], o);
    float m = fmaxf(fmaxf(pe[0], pe[1]), fmaxf(pe[2], pe[3]));
    float e0 = expf(pe[0]-m), e1 = expf(pe[1]-m), e2 = expf(pe[2]-m), e3 = expf(pe[3]-m);
    float denom = e0 + e1 + e2 + e3;
    if (lane == 0) {
        float* gp = &g_gates[(size_t)gwarp*CE];
        gp[0] = e0/denom; gp[1] = e1/denom; gp[2] = e2/denom; gp[3] = e3/denom;
    }
}

// ---------------------------------------------------------------------------
// K11: combine (xc + delta) transpose back to (bt,d,h,w) + residual -> out
// ---------------------------------------------------------------------------
__global__ void k_combine(float2* __restrict__ out)
{
    __shared__ float2 sm[32][65];
    int pix0 = blockIdx.x * 32;
    int bt = pix0 / CHW, hw0 = pix0 % CHW;
    int tid = threadIdx.x;
    #pragma unroll
    for (int i = 0; i < 8; i++) {
        int lin = tid + i*256;
        int p = lin >> 6, d = lin & 63;
        size_t gi = (size_t)(pix0 + p)*CD + d;
        float2 v  = g_xc[gi];
        float2 dl = g_xeig[gi];
        sm[p][d] = make_float2(v.x + dl.x, v.y + dl.y);
    }
    __syncthreads();
    #pragma unroll
    for (int i = 0; i < 8; i++) {
        int lin = tid + i*256;
        int p = lin & 31, d = lin >> 5;
        size_t gi = (size_t)(bt*CD + d)*CHW + hw0 + p;
        float2 v = sm[p][d];
        out[gi] = make_float2(g_xs_re[gi] + v.x, g_xs_im[gi] + v.y);
    }
}

// ---------------------------------------------------------------------------
// Host launcher
// ---------------------------------------------------------------------------
extern "C" void kernel_launch(void* const* d_in, const int* in_sizes, int n_in,
                              void* d_out, int out_size)
{
    const float* x_re   = (const float*)d_in[0];
    const float* x_im   = (const float*)d_in[1];
    const float* hp_re  = (const float*)d_in[2];
    const float* hp_im  = (const float*)d_in[3];
    const float* dt     = (const float*)d_in[4];
    const float* fp_re  = (const float*)d_in[5];
    const float* fp_im  = (const float*)d_in[6];
    const float* lnsp_w = (const float*)d_in[7];
    const float* lnsp_b = (const float*)d_in[8];
    const float* conv_w = (const float*)d_in[9];
    const float* conv_b = (const float*)d_in[10];
    const float* metric = (const float*)d_in[11];
    const float* lnt_w  = (const float*)d_in[12];
    const float* lnt_b  = (const float*)d_in[13];
    const float* Eenc_r = (const float*)d_in[14];
    const float* Eenc_i = (const float*)d_in[15];
    const float* Edec_r = (const float*)d_in[16];
    const float* Edec_i = (const float*)d_in[17];
    const float* Wg     = (const float*)d_in[18];
    const float* bg     = (const float*)d_in[19];
    const float* al_re  = (const float*)d_in[20];
    const float* al_im  = (const float*)d_in[21];
    const float* lam_nu = (const float*)d_in[22];
    const float* lam_im = (const float*)d_in[23];
    const float* Wgate  = (const float*)d_in[24];
    const float* W1_re  = (const float*)d_in[25];
    const float* W1_im  = (const float*)d_in[26];
    const float* W2_re  = (const float*)d_in[27];
    const float* W2_im  = (const float*)d_in[28];

    float2 *p_xeig = 0, *p_xc = 0, *p_act = 0;
    float  *p_xsre = 0, *p_xsim = 0, *p_gates = 0;
    cudaGetSymbolAddress((void**)&p_xeig,  g_xeig);
    cudaGetSymbolAddress((void**)&p_xc,    g_xc);
    cudaGetSymbolAddress((void**)&p_act,   g_act);
    cudaGetSymbolAddress((void**)&p_xsre,  g_xs_re);
    cudaGetSymbolAddress((void**)&p_xsim,  g_xs_im);
    cudaGetSymbolAddress((void**)&p_gates, g_gates);

    // 1. spatial LN + metric
    k_ln_spatial<<<(NPIX + 255)/256, 256>>>(x_re, x_im, lnsp_w, lnsp_b, metric);

    // 2. conv 3x3 as implicit GEMM on tensor cores
    k_conv_mma<<<NPIX/128, 256>>>(conv_w, conv_b, x_re, x_im);

    // 3. x_eig = xs @ E_enc   (planar A, tensor cores)
    k_mma<1,0><<<dim3(1, NPIX/128, 1), 256>>>(
        nullptr, p_xsre, p_xsim, Eenc_r, Eenc_i, p_xeig, nullptr,
        CD, 0, CD, CD, 0, 0);

    // 4. partial mean over H*W
    k_mean_part<<<dim3(CBT, 12), 256>>>();

    // 5. mean finalize + flux scan + coefficients
    k_scan<<<1, 128>>>(dt, fp_re, fp_im, Wg, bg, al_re, al_im, lam_nu, lam_im);

    // 6. forcing + temporal scan + h_prev
    k_temporal<<<(CB*CHW*CD + 255)/256, 256>>>(hp_re, hp_im);

    // 7. xc_raw = u @ E_dec
    k_mma<0,0><<<dim3(1, NPIX/128, 1), 256>>>(
        (const float*)p_xeig, nullptr, nullptr, Edec_r, Edec_i, p_xc, nullptr,
        CD, 2*CD, CD, CD, 0, 0);

    // 8. temporal LN (in-place) + softmax gates
    k_ln2gate<<<NPIX/8, 256>>>(lnt_w, lnt_b, Wgate);

    // 9. h1 per e (gelu * gate epilogue) -> g_act (m, e*F+f)
    k_mma<0,1><<<dim3(CF/64, NPIX/128, CE), 256>>>(
        (const float*)p_xc, nullptr, nullptr, W1_re, W1_im, p_act, p_gates,
        CD, 2*CD, CF, CE*CF, CD*CF, CF);

    // 10. delta = a_scaled @ W2(viewed as (E*F, D)) -> g_xeig (reuse)
    k_mma<0,0><<<dim3(1, NPIX/128, 1), 256>>>(
        (const float*)p_act, nullptr, nullptr, W2_re, W2_im, p_xeig, nullptr,
        CE*CF, 2*CE*CF, CD, CD, 0, 0);

    // 11. combine + transpose + final residual -> out
    k_combine<<<NPIX/32, 256>>>((float2*)d_out);
}